// round 2
// baseline (speedup 1.0000x reference)
#include <cuda_runtime.h>
#include <math.h>

// ---------------- problem constants ----------------
namespace {
constexpr int kN   = 50625;          // SIDE^4
constexpr int kB   = 16;             // batch
constexpr int kDim = 16;
constexpr int kH   = 8;
constexpr int kDH  = 4;
constexpr int kFFD = 64;
constexpr int kBot = 26;
constexpr int kL   = 6;
constexpr int kTPB = 256;
constexpr int kBPB = (kN + kTPB - 1) / kTPB;   // 198 blocks per batch
constexpr int kGrid = kB * kBPB;               // 3168
constexpr float kScale = 0.5f;                 // DH^-0.5
}

// ---------------- scratch (device globals; no allocation) ----------------
__device__ float g_x[(size_t)kB * kN * kDim];      // token states, 51.8 MB
__device__ float g_partQ[kGrid * 40];              // per-block partial sums (stage A)
__device__ float g_partK[kGrid * 40];              // per-block partial sums (stage B)

// ---------------- helpers ----------------
__device__ __forceinline__ void ln16(const float* x, const float* g,
                                     const float* bb, float* y) {
  float m = 0.f;
#pragma unroll
  for (int d = 0; d < 16; d++) m += x[d];
  m *= (1.f / 16.f);
  float v = 0.f;
#pragma unroll
  for (int d = 0; d < 16; d++) { float t = x[d] - m; v = fmaf(t, t, v); }
  v *= (1.f / 16.f);
  float r = rsqrtf(v + 1e-5f);
#pragma unroll
  for (int d = 0; d < 16; d++) y[d] = (x[d] - m) * r * g[d] + bb[d];
}

// rotary cos/sin reproducing fp32 semantics of cos(fl32(n*pi32)), etc.
// cos(n*pi + delta) = (-1)^n cos(delta);  delta computed in double, tiny.
__device__ __forceinline__ void rot_cs(int n, float& c0, float& s0,
                                       float& c1, float& s1) {
  float nf = (float)n;
  float p0 = nf * 3.14159265358979323846f;   // fl32(n * fl32(pi))
  float p1 = nf * 15.70796326794896619231f;  // fl32(n * fl32(5*pi))
  double d0 = (double)p0 - (double)n * 3.14159265358979323846;
  double d1 = (double)p1 - (double)n * 15.70796326794896619231;
  float e0 = (float)d0, e1 = (float)d1;
  float sgn = (n & 1) ? -1.f : 1.f;          // parity of n == parity of 5n
  c0 = sgn * (1.f - 0.5f * e0 * e0);
  s0 = sgn * e0 * (1.f - 0.1666666667f * e0 * e0);
  c1 = sgn * (1.f - 0.5f * e1 * e1);
  s1 = sgn * e1 * (1.f - 0.1666666667f * e1 * e1);
}

// deterministic block reduction of 40 per-thread floats -> 40 global floats
__device__ __forceinline__ void reduce40(float* vals, float* out) {
  __shared__ float s_red[8][40];
  int lane = threadIdx.x & 31, w = threadIdx.x >> 5;
#pragma unroll
  for (int k = 0; k < 40; k++) {
    float v = vals[k];
    v += __shfl_down_sync(0xffffffffu, v, 16);
    v += __shfl_down_sync(0xffffffffu, v, 8);
    v += __shfl_down_sync(0xffffffffu, v, 4);
    v += __shfl_down_sync(0xffffffffu, v, 2);
    v += __shfl_down_sync(0xffffffffu, v, 1);
    if (lane == 0) s_red[w][k] = v;
  }
  __syncthreads();
  if (threadIdx.x < 40) {
    float s = 0.f;
#pragma unroll
    for (int w2 = 0; w2 < 8; w2++) s += s_red[w2][threadIdx.x];
    out[threadIdx.x] = s;
  }
}

// dot of y[16] with transposed weight row (contiguous 16 floats, float4 loads)
__device__ __forceinline__ float dot16(const float* y, const float* wrow) {
  float a = 0.f;
#pragma unroll
  for (int d4 = 0; d4 < 4; d4++) {
    float4 w = *reinterpret_cast<const float4*>(wrow + 4 * d4);
    a = fmaf(y[4*d4+0], w.x, a);
    a = fmaf(y[4*d4+1], w.y, a);
    a = fmaf(y[4*d4+2], w.z, a);
    a = fmaf(y[4*d4+3], w.w, a);
  }
  return a;
}

// ---------------- kernels ----------------
__global__ void __launch_bounds__(kTPB) embed_kernel(
    const float* __restrict__ corr, const float* __restrict__ W_emb,
    const float* __restrict__ b_emb) {
  __shared__ float sW[kBot * kDim];
  __shared__ float sb[kDim];
  for (int i = threadIdx.x; i < kBot * kDim; i += kTPB) sW[i] = W_emb[i];
  if (threadIdx.x < kDim) sb[threadIdx.x] = b_emb[threadIdx.x];
  __syncthreads();
  int b = blockIdx.x / kBPB;
  int n = (blockIdx.x % kBPB) * kTPB + threadIdx.x;
  if (n >= kN) return;
  float x[kDim];
#pragma unroll
  for (int d = 0; d < kDim; d++) x[d] = sb[d];
  const float* cp = corr + (size_t)b * kBot * kN + n;
#pragma unroll 13
  for (int c = 0; c < kBot; c++) {
    float v = fmaxf(cp[(size_t)c * kN], 0.f);
#pragma unroll
    for (int d4 = 0; d4 < 4; d4++) {
      float4 w = *reinterpret_cast<const float4*>(&sW[c * kDim + 4 * d4]);
      x[4*d4+0] = fmaf(v, w.x, x[4*d4+0]);
      x[4*d4+1] = fmaf(v, w.y, x[4*d4+1]);
      x[4*d4+2] = fmaf(v, w.z, x[4*d4+2]);
      x[4*d4+3] = fmaf(v, w.w, x[4*d4+3]);
    }
  }
  float* xp = g_x + (size_t)(b * kN + n) * kDim;
#pragma unroll
  for (int d = 0; d < kDim; d += 4)
    *reinterpret_cast<float4*>(xp + d) = make_float4(x[d], x[d+1], x[d+2], x[d+3]);
}

// Stage A: per-token q, rotary-q, q-logit; block-partial softmax stats
__global__ void __launch_bounds__(kTPB) stageA_kernel(
    const float* __restrict__ Wqkv, const float* __restrict__ ln1g,
    const float* __restrict__ ln1b, const float* __restrict__ wqlog) {
  __shared__ float sW[32 * 16];   // transposed: [col][dim]
  __shared__ float sg[16], sb[16], swq[4];
  for (int i = threadIdx.x; i < 512; i += kTPB) {
    int c = i >> 4, d = i & 15;
    sW[i] = Wqkv[d * 96 + c];     // q cols 0..31
  }
  if (threadIdx.x < 16) { sg[threadIdx.x] = ln1g[threadIdx.x]; sb[threadIdx.x] = ln1b[threadIdx.x]; }
  if (threadIdx.x < 4) swq[threadIdx.x] = wqlog[threadIdx.x];
  __syncthreads();
  int b = blockIdx.x / kBPB;
  int n = (blockIdx.x % kBPB) * kTPB + threadIdx.x;
  float vals[40];
#pragma unroll
  for (int k = 0; k < 40; k++) vals[k] = 0.f;
  if (n < kN) {
    const float* xp = g_x + (size_t)(b * kN + n) * kDim;
    float x[16], y[16];
#pragma unroll
    for (int d = 0; d < 16; d += 4) {
      float4 t = *reinterpret_cast<const float4*>(xp + d);
      x[d] = t.x; x[d+1] = t.y; x[d+2] = t.z; x[d+3] = t.w;
    }
    ln16(x, sg, sb, y);
    float c0, s0, c1, s1; rot_cs(n, c0, s0, c1, s1);
#pragma unroll
    for (int h = 0; h < 8; h++) {
      float q0 = dot16(y, &sW[(4*h+0)*16]);
      float q1 = dot16(y, &sW[(4*h+1)*16]);
      float q2 = dot16(y, &sW[(4*h+2)*16]);
      float q3 = dot16(y, &sW[(4*h+3)*16]);
      float lg = (q0*swq[0] + q1*swq[1] + q2*swq[2] + q3*swq[3]) * kScale;
      float e = expf(lg);
      float r0 = q0*c0 - q1*s0, r1 = q1*c0 + q0*s0;
      float r2 = q2*c1 - q3*s1, r3 = q3*c1 + q2*s1;
      vals[h*5+0] = e;
      vals[h*5+1] = e*r0; vals[h*5+2] = e*r1;
      vals[h*5+3] = e*r2; vals[h*5+4] = e*r3;
    }
  }
  reduce40(vals, g_partQ + (size_t)blockIdx.x * 40);
}

// Stage B: finish q-softmax (global_q), per-token k, k2 logits; partial stats
__global__ void __launch_bounds__(kTPB) stageB_kernel(
    const float* __restrict__ Wqkv, const float* __restrict__ ln1g,
    const float* __restrict__ ln1b, const float* __restrict__ wklog) {
  __shared__ float sW[32 * 16];   // transposed k cols
  __shared__ float sg[16], sb[16], swk[2];
  __shared__ float sgq[32];       // global_q [h][d]
  for (int i = threadIdx.x; i < 512; i += kTPB) {
    int c = i >> 4, d = i & 15;
    sW[i] = Wqkv[d * 96 + 32 + c];
  }
  if (threadIdx.x < 16) { sg[threadIdx.x] = ln1g[threadIdx.x]; sb[threadIdx.x] = ln1b[threadIdx.x]; }
  if (threadIdx.x < 2) swk[threadIdx.x] = wklog[threadIdx.x];
  int b = blockIdx.x / kBPB;
  if (threadIdx.x < 32) {
    int h = threadIdx.x >> 2, d = threadIdx.x & 3;
    float den = 0.f, num = 0.f;
    const float* pp = g_partQ + (size_t)b * kBPB * 40;
    for (int blk = 0; blk < kBPB; blk++) {
      den += pp[blk*40 + h*5];
      num += pp[blk*40 + h*5 + 1 + d];
    }
    sgq[threadIdx.x] = num / den;
  }
  __syncthreads();
  int n = (blockIdx.x % kBPB) * kTPB + threadIdx.x;
  float vals[40];
#pragma unroll
  for (int k = 0; k < 40; k++) vals[k] = 0.f;
  if (n < kN) {
    const float* xp = g_x + (size_t)(b * kN + n) * kDim;
    float x[16], y[16];
#pragma unroll
    for (int d = 0; d < 16; d += 4) {
      float4 t = *reinterpret_cast<const float4*>(xp + d);
      x[d] = t.x; x[d+1] = t.y; x[d+2] = t.z; x[d+3] = t.w;
    }
    ln16(x, sg, sb, y);
    float c0, s0, c1, s1; rot_cs(n, c0, s0, c1, s1);
#pragma unroll
    for (int h = 0; h < 8; h++) {
      float k0 = dot16(y, &sW[(4*h+0)*16]);
      float k1 = dot16(y, &sW[(4*h+1)*16]);
      float k2v = dot16(y, &sW[(4*h+2)*16]);
      float k3 = dot16(y, &sW[(4*h+3)*16]);
      float p0 = k0*sgq[4*h+0] + k1*sgq[4*h+1];
      float p1 = k2v*sgq[4*h+2] + k3*sgq[4*h+3];
      float lg = (p0*swk[0] + p1*swk[1]) * kScale;
      float e = expf(lg);
      float r0 = k0*c0 - k1*s0, r1 = k1*c0 + k0*s0;
      float r2 = k2v*c1 - k3*s1, r3 = k3*c1 + k2v*s1;
      vals[h*5+0] = e;
      vals[h*5+1] = e*r0; vals[h*5+2] = e*r1;
      vals[h*5+3] = e*r2; vals[h*5+4] = e*r3;
    }
  }
  reduce40(vals, g_partK + (size_t)blockIdx.x * 40);
}

// Stage C: finish k-softmax (global_k), attention output, residual, FF, residual
__global__ void __launch_bounds__(kTPB) stageC_kernel(
    const float* __restrict__ Wqkv, const float* __restrict__ ln1g,
    const float* __restrict__ ln1b,
    const float* __restrict__ Wr, const float* __restrict__ br,
    const float* __restrict__ Wo, const float* __restrict__ bo,
    const float* __restrict__ ln2g, const float* __restrict__ ln2b,
    const float* __restrict__ W1, const float* __restrict__ b1,
    const float* __restrict__ W2, const float* __restrict__ b2,
    const float* __restrict__ Wout, const float* __restrict__ bout,
    float* __restrict__ out, int last) {
  __shared__ float sWq[32 * 16], sWv[32 * 16];   // transposed
  __shared__ float sWo[32 * 16];                 // natural [c][d]
  __shared__ float sW1[64 * 16];                 // transposed [j][d]
  __shared__ float sW2[64 * 16];                 // natural [j][d]
  __shared__ float sg1[16], sb1g[16], sg2[16], sb2g[16];
  __shared__ float sWr[8], sbr[4], sbo[16], sB1[64], sB2[16];
  __shared__ float sgk[32], swout[16];
  __shared__ float sbout;

  for (int i = threadIdx.x; i < 512; i += kTPB) {
    int c = i >> 4, d = i & 15;
    sWq[i] = Wqkv[d * 96 + c];
    sWv[i] = Wqkv[d * 96 + 64 + c];
    sWo[i] = Wo[i];                 // (32,16) row-major: row c contiguous in d
  }
  for (int i = threadIdx.x; i < 1024; i += kTPB) {
    int j = i >> 4, d = i & 15;
    sW1[i] = W1[d * 64 + j];        // transpose (16,64) -> [j][d]
    sW2[i] = W2[i];                 // (64,16) row-major
  }
  if (threadIdx.x < 16) {
    int i = threadIdx.x;
    sg1[i] = ln1g[i]; sb1g[i] = ln1b[i];
    sg2[i] = ln2g[i]; sb2g[i] = ln2b[i];
    sbo[i] = bo[i]; sB2[i] = b2[i]; swout[i] = Wout[i];
  }
  if (threadIdx.x < 64) sB1[threadIdx.x] = b1[threadIdx.x];
  if (threadIdx.x < 8) sWr[threadIdx.x] = Wr[threadIdx.x];
  if (threadIdx.x < 4) sbr[threadIdx.x] = br[threadIdx.x];
  if (threadIdx.x == 0) sbout = bout[0];
  int b = blockIdx.x / kBPB;
  if (threadIdx.x >= 64 && threadIdx.x < 96) {
    int t = threadIdx.x - 64;
    int h = t >> 2, d = t & 3;
    float den = 0.f, num = 0.f;
    const float* pp = g_partK + (size_t)b * kBPB * 40;
    for (int blk = 0; blk < kBPB; blk++) {
      den += pp[blk*40 + h*5];
      num += pp[blk*40 + h*5 + 1 + d];
    }
    sgk[t] = num / den;
  }
  __syncthreads();

  int n = (blockIdx.x % kBPB) * kTPB + threadIdx.x;
  if (n >= kN) return;

  float* xp = g_x + (size_t)(b * kN + n) * kDim;
  float x[16], y[16];
#pragma unroll
  for (int d = 0; d < 16; d += 4) {
    float4 t = *reinterpret_cast<const float4*>(xp + d);
    x[d] = t.x; x[d+1] = t.y; x[d+2] = t.z; x[d+3] = t.w;
  }
  ln16(x, sg1, sb1g, y);

  // attention value path per head
  float r[32];
#pragma unroll
  for (int h = 0; h < 8; h++) {
    float q0 = dot16(y, &sWq[(4*h+0)*16]);
    float q1 = dot16(y, &sWq[(4*h+1)*16]);
    float q2 = dot16(y, &sWq[(4*h+2)*16]);
    float q3 = dot16(y, &sWq[(4*h+3)*16]);
    float v0 = dot16(y, &sWv[(4*h+0)*16]);
    float v1 = dot16(y, &sWv[(4*h+1)*16]);
    float v2 = dot16(y, &sWv[(4*h+2)*16]);
    float v3 = dot16(y, &sWv[(4*h+3)*16]);
    float u0 = v0*sgk[4*h+0] + v1*sgk[4*h+1];
    float u1 = v2*sgk[4*h+2] + v3*sgk[4*h+3];
    r[4*h+0] = fmaf(u0, sWr[0], fmaf(u1, sWr[4], sbr[0])) + q0;
    r[4*h+1] = fmaf(u0, sWr[1], fmaf(u1, sWr[5], sbr[1])) + q1;
    r[4*h+2] = fmaf(u0, sWr[2], fmaf(u1, sWr[6], sbr[2])) + q2;
    r[4*h+3] = fmaf(u0, sWr[3], fmaf(u1, sWr[7], sbr[3])) + q3;
  }

  // x += r @ W_o + b_o
  float acc[16];
#pragma unroll
  for (int d = 0; d < 16; d++) acc[d] = sbo[d];
#pragma unroll
  for (int c = 0; c < 32; c++) {
    float rc = r[c];
#pragma unroll
    for (int d4 = 0; d4 < 4; d4++) {
      float4 w = *reinterpret_cast<const float4*>(&sWo[c * 16 + 4 * d4]);
      acc[4*d4+0] = fmaf(rc, w.x, acc[4*d4+0]);
      acc[4*d4+1] = fmaf(rc, w.y, acc[4*d4+1]);
      acc[4*d4+2] = fmaf(rc, w.z, acc[4*d4+2]);
      acc[4*d4+3] = fmaf(rc, w.w, acc[4*d4+3]);
    }
  }
#pragma unroll
  for (int d = 0; d < 16; d++) x[d] += acc[d];

  // FF block
  float y2[16];
  ln16(x, sg2, sb2g, y2);
#pragma unroll
  for (int d = 0; d < 16; d++) acc[d] = sB2[d];
#pragma unroll 8
  for (int j = 0; j < 64; j++) {
    float p = sB1[j] + dot16(y2, &sW1[j * 16]);
    float hj = 0.5f * p * (1.f + erff(p * 0.7071067811865475f));
#pragma unroll
    for (int d4 = 0; d4 < 4; d4++) {
      float4 w = *reinterpret_cast<const float4*>(&sW2[j * 16 + 4 * d4]);
      acc[4*d4+0] = fmaf(hj, w.x, acc[4*d4+0]);
      acc[4*d4+1] = fmaf(hj, w.y, acc[4*d4+1]);
      acc[4*d4+2] = fmaf(hj, w.z, acc[4*d4+2]);
      acc[4*d4+3] = fmaf(hj, w.w, acc[4*d4+3]);
    }
  }
#pragma unroll
  for (int d = 0; d < 16; d++) x[d] += acc[d];

  if (last) {
    float o = sbout;
#pragma unroll
    for (int d = 0; d < 16; d++) o = fmaf(x[d], swout[d], o);
    out[(size_t)b * kN + n] = o;
  } else {
#pragma unroll
    for (int d = 0; d < 16; d += 4)
      *reinterpret_cast<float4*>(xp + d) = make_float4(x[d], x[d+1], x[d+2], x[d+3]);
  }
}

// ---------------- host launcher ----------------
extern "C" void kernel_launch(void* const* d_in, const int* in_sizes, int n_in,
                              void* d_out, int out_size) {
  (void)in_sizes; (void)n_in; (void)out_size;
  const float* corr  = (const float*)d_in[0];
  const float* W_emb = (const float*)d_in[1];
  const float* b_emb = (const float*)d_in[2];
  const float* ln1_g = (const float*)d_in[3];
  const float* ln1_b = (const float*)d_in[4];
  const float* W_qkv = (const float*)d_in[5];
  const float* w_qlog= (const float*)d_in[6];
  const float* w_klog= (const float*)d_in[7];
  const float* W_r   = (const float*)d_in[8];
  const float* b_r   = (const float*)d_in[9];
  const float* W_o   = (const float*)d_in[10];
  const float* b_o   = (const float*)d_in[11];
  const float* ln2_g = (const float*)d_in[12];
  const float* ln2_b = (const float*)d_in[13];
  const float* W_ff1 = (const float*)d_in[14];
  const float* b_ff1 = (const float*)d_in[15];
  const float* W_ff2 = (const float*)d_in[16];
  const float* b_ff2 = (const float*)d_in[17];
  const float* W_out = (const float*)d_in[18];
  const float* b_out = (const float*)d_in[19];
  float* out = (float*)d_out;

  embed_kernel<<<kGrid, kTPB>>>(corr, W_emb, b_emb);
  for (int i = 0; i < kL; i++) {
    const float* Wq = W_qkv + (size_t)i * 16 * 96;
    stageA_kernel<<<kGrid, kTPB>>>(Wq, ln1_g + i*16, ln1_b + i*16, w_qlog + i*4);
    stageB_kernel<<<kGrid, kTPB>>>(Wq, ln1_g + i*16, ln1_b + i*16, w_klog + i*2);
    stageC_kernel<<<kGrid, kTPB>>>(Wq, ln1_g + i*16, ln1_b + i*16,
        W_r + i*8, b_r + i*4, W_o + i*512, b_o + i*16,
        ln2_g + i*16, ln2_b + i*16,
        W_ff1 + (size_t)i*16*64, b_ff1 + i*64,
        W_ff2 + (size_t)i*64*16, b_ff2 + i*16,
        W_out, b_out, out, (i == kL - 1) ? 1 : 0);
  }
}

// round 3
// speedup vs baseline: 1.3960x; 1.3960x over previous
#include <cuda_runtime.h>
#include <math.h>

// ---------------- problem constants ----------------
namespace {
constexpr int kN   = 50625;          // SIDE^4
constexpr int kB   = 16;             // batch
constexpr int kBot = 26;
constexpr int kL   = 6;
constexpr int kTPB = 256;
constexpr int kBPB = (kN + kTPB - 1) / kTPB;   // 198 blocks per batch
constexpr int kGrid = kB * kBPB;               // 3168
constexpr float kScale = 0.5f;                 // DH^-0.5
constexpr int kStride = 4288;                  // floats per staged layer block
}

typedef unsigned long long u64;

// ---------------- per-layer constant parameter bank ----------------
struct CParams {
  float Wqkv[1536];                  // (16,96) natural
  float Wo[512];                     // (32,16) natural
  float W1[1024];                    // (16,64) natural
  float W2[1024];                    // (64,16) natural
  float ln1g[16], ln1b[16], ln2g[16], ln2b[16];
  float wq[4], wk[2], pad0[2];
  float Wr[8];
  float br[4], bo[16], B1[64], B2[16];
  float pad1[12];                    // -> 4288 floats total
};
static_assert(sizeof(CParams) == kStride * sizeof(float), "layout");

__constant__ CParams cP;
__constant__ float cWemb[kBot * 16];
__constant__ float cbemb[16];
__constant__ float cWout[16];
__constant__ float cbout[4];

// ---------------- scratch (device globals; no allocation) ----------------
__device__ float g_x[(size_t)kB * kN * 16];        // token states
__device__ float g_partQ[kGrid * 40];
__device__ float g_partK[kGrid * 40];
__device__ float g_gq[kB * 32];
__device__ float g_gk[kB * 32];
__device__ float g_stage[kL * kStride];

// ---------------- packed f32x2 helpers ----------------
__device__ __forceinline__ u64 pack2(float lo, float hi) {
  u64 r; asm("mov.b64 %0,{%1,%2};" : "=l"(r) : "f"(lo), "f"(hi)); return r;
}
__device__ __forceinline__ void unpack2(u64 v, float& lo, float& hi) {
  asm("mov.b64 {%0,%1},%2;" : "=f"(lo), "=f"(hi) : "l"(v));
}
__device__ __forceinline__ u64 fma2(u64 a, u64 b, u64 c) {
  u64 d; asm("fma.rn.f32x2 %0,%1,%2,%3;" : "=l"(d) : "l"(a), "l"(b), "l"(c)); return d;
}
__device__ __forceinline__ u64 ldc2(const float* p) {
  return *reinterpret_cast<const u64*>(p);
}

// ---------------- scalar helpers ----------------
__device__ __forceinline__ void ln16(const float* x, const float* g,
                                     const float* bb, float* y) {
  float m = 0.f;
#pragma unroll
  for (int d = 0; d < 16; d++) m += x[d];
  m *= (1.f / 16.f);
  float v = 0.f;
#pragma unroll
  for (int d = 0; d < 16; d++) { float t = x[d] - m; v = fmaf(t, t, v); }
  v *= (1.f / 16.f);
  float r = rsqrtf(v + 1e-5f);
#pragma unroll
  for (int d = 0; d < 16; d++) y[d] = (x[d] - m) * r * g[d] + bb[d];
}

// rotary cos/sin reproducing fp32 semantics of cos(fl32(n*pi32)) etc.
__device__ __forceinline__ void rot_cs(int n, float& c0, float& s0,
                                       float& c1, float& s1) {
  float nf = (float)n;
  float p0 = nf * 3.14159265358979323846f;
  float p1 = nf * 15.70796326794896619231f;
  double d0 = (double)p0 - (double)n * 3.14159265358979323846;
  double d1 = (double)p1 - (double)n * 15.70796326794896619231;
  float e0 = (float)d0, e1 = (float)d1;
  float sgn = (n & 1) ? -1.f : 1.f;
  c0 = sgn * (1.f - 0.5f * e0 * e0);
  s0 = sgn * e0 * (1.f - 0.1666666667f * e0 * e0);
  c1 = sgn * (1.f - 0.5f * e1 * e1);
  s1 = sgn * e1 * (1.f - 0.1666666667f * e1 * e1);
}

// deterministic block reduction of 40 per-thread floats -> 40 global floats
__device__ __forceinline__ void reduce40(float* vals, float* out) {
  __shared__ float s_red[8][40];
  int lane = threadIdx.x & 31, w = threadIdx.x >> 5;
#pragma unroll
  for (int k = 0; k < 40; k++) {
    float v = vals[k];
    v += __shfl_down_sync(0xffffffffu, v, 16);
    v += __shfl_down_sync(0xffffffffu, v, 8);
    v += __shfl_down_sync(0xffffffffu, v, 4);
    v += __shfl_down_sync(0xffffffffu, v, 2);
    v += __shfl_down_sync(0xffffffffu, v, 1);
    if (lane == 0) s_red[w][k] = v;
  }
  __syncthreads();
  if (threadIdx.x < 40) {
    float s = 0.f;
#pragma unroll
    for (int w2 = 0; w2 < 8; w2++) s += s_red[w2][threadIdx.x];
    out[threadIdx.x] = s;
  }
}

// ---------------- gather: stage per-layer weights contiguously ----------------
__global__ void gather_kernel(
    const float* __restrict__ Wqkv, const float* __restrict__ ln1g,
    const float* __restrict__ ln1b, const float* __restrict__ wq,
    const float* __restrict__ wk, const float* __restrict__ Wr,
    const float* __restrict__ br, const float* __restrict__ Wo,
    const float* __restrict__ bo, const float* __restrict__ ln2g,
    const float* __restrict__ ln2b, const float* __restrict__ W1,
    const float* __restrict__ b1, const float* __restrict__ W2,
    const float* __restrict__ b2) {
  int i = blockIdx.x;
  float* s = &g_stage[(size_t)i * kStride];
  int t = threadIdx.x;
  for (int k = t; k < 1536; k += kTPB) s[k]        = Wqkv[i * 1536 + k];
  for (int k = t; k < 512;  k += kTPB) s[1536 + k] = Wo[i * 512 + k];
  for (int k = t; k < 1024; k += kTPB) s[2048 + k] = W1[i * 1024 + k];
  for (int k = t; k < 1024; k += kTPB) s[3072 + k] = W2[i * 1024 + k];
  if (t < 16) {
    s[4096 + t] = ln1g[i * 16 + t];
    s[4112 + t] = ln1b[i * 16 + t];
    s[4128 + t] = ln2g[i * 16 + t];
    s[4144 + t] = ln2b[i * 16 + t];
    s[4180 + t] = bo[i * 16 + t];
    s[4260 + t] = b2[i * 16 + t];
  }
  if (t < 4) { s[4160 + t] = wq[i * 4 + t]; s[4176 + t] = br[i * 4 + t]; }
  if (t < 2) { s[4164 + t] = wk[i * 2 + t]; }
  if (t < 8) { s[4168 + t] = Wr[i * 8 + t]; }
  if (t < 64) { s[4196 + t] = b1[i * 64 + t]; }
}

// ---------------- embed ----------------
__global__ void __launch_bounds__(kTPB) embed_kernel(const float* __restrict__ corr) {
  int b = blockIdx.x / kBPB;
  int n = (blockIdx.x % kBPB) * kTPB + threadIdx.x;
  if (n >= kN) return;
  u64 acc[8];
#pragma unroll
  for (int d2 = 0; d2 < 8; d2++) acc[d2] = ldc2(&cbemb[2 * d2]);
  const float* cp = corr + (size_t)b * kBot * kN + n;
#pragma unroll 13
  for (int c = 0; c < kBot; c++) {
    float v = fmaxf(cp[(size_t)c * kN], 0.f);
    u64 v2 = pack2(v, v);
#pragma unroll
    for (int d2 = 0; d2 < 8; d2++)
      acc[d2] = fma2(ldc2(&cWemb[c * 16 + 2 * d2]), v2, acc[d2]);
  }
  float* xp = g_x + (size_t)(b * kN + n) * 16;
#pragma unroll
  for (int d2 = 0; d2 < 8; d2++)
    *reinterpret_cast<u64*>(xp + 2 * d2) = acc[d2];
}

// ---------------- stage A: q stats ----------------
__global__ void __launch_bounds__(kTPB) stageA_kernel() {
  int b = blockIdx.x / kBPB;
  int n = (blockIdx.x % kBPB) * kTPB + threadIdx.x;
  float vals[40];
#pragma unroll
  for (int k = 0; k < 40; k++) vals[k] = 0.f;
  if (n < kN) {
    const float* xp = g_x + (size_t)(b * kN + n) * 16;
    float x[16], y[16];
#pragma unroll
    for (int d = 0; d < 16; d += 4) {
      float4 t = *reinterpret_cast<const float4*>(xp + d);
      x[d] = t.x; x[d+1] = t.y; x[d+2] = t.z; x[d+3] = t.w;
    }
    ln16(x, cP.ln1g, cP.ln1b, y);
    u64 acc[16];
#pragma unroll
    for (int c = 0; c < 16; c++) acc[c] = 0ull;
#pragma unroll
    for (int d = 0; d < 16; d++) {
      u64 yd = pack2(y[d], y[d]);
#pragma unroll
      for (int c = 0; c < 16; c++)
        acc[c] = fma2(ldc2(&cP.Wqkv[d * 96 + 2 * c]), yd, acc[c]);
    }
    float q[32];
#pragma unroll
    for (int c = 0; c < 16; c++) unpack2(acc[c], q[2*c], q[2*c+1]);
    float c0, s0, c1, s1; rot_cs(n, c0, s0, c1, s1);
#pragma unroll
    for (int h = 0; h < 8; h++) {
      float q0 = q[4*h], q1 = q[4*h+1], q2 = q[4*h+2], q3 = q[4*h+3];
      float lg = (q0*cP.wq[0] + q1*cP.wq[1] + q2*cP.wq[2] + q3*cP.wq[3]) * kScale;
      float e = expf(lg);
      float r0 = q0*c0 - q1*s0, r1 = q1*c0 + q0*s0;
      float r2 = q2*c1 - q3*s1, r3 = q3*c1 + q2*s1;
      vals[h*5+0] = e;
      vals[h*5+1] = e*r0; vals[h*5+2] = e*r1;
      vals[h*5+3] = e*r2; vals[h*5+4] = e*r3;
    }
  }
  reduce40(vals, g_partQ + (size_t)blockIdx.x * 40);
}

// ---------------- finalize softmax stats -> global vectors ----------------
__global__ void finalizeQ_kernel() {
  __shared__ float s[40];
  int b = blockIdx.x;
  if (threadIdx.x < 40) {
    float acc = 0.f;
    const float* pp = g_partQ + (size_t)b * kBPB * 40 + threadIdx.x;
    for (int blk = 0; blk < kBPB; blk++) acc += pp[blk * 40];
    s[threadIdx.x] = acc;
  }
  __syncthreads();
  if (threadIdx.x < 32) {
    int h = threadIdx.x >> 2, d = threadIdx.x & 3;
    g_gq[b * 32 + threadIdx.x] = s[h*5+1+d] / s[h*5];
  }
}
__global__ void finalizeK_kernel() {
  __shared__ float s[40];
  int b = blockIdx.x;
  if (threadIdx.x < 40) {
    float acc = 0.f;
    const float* pp = g_partK + (size_t)b * kBPB * 40 + threadIdx.x;
    for (int blk = 0; blk < kBPB; blk++) acc += pp[blk * 40];
    s[threadIdx.x] = acc;
  }
  __syncthreads();
  if (threadIdx.x < 32) {
    int h = threadIdx.x >> 2, d = threadIdx.x & 3;
    g_gk[b * 32 + threadIdx.x] = s[h*5+1+d] / s[h*5];
  }
}

// ---------------- stage B: k stats ----------------
__global__ void __launch_bounds__(kTPB) stageB_kernel() {
  __shared__ float sgq[32];
  int b = blockIdx.x / kBPB;
  if (threadIdx.x < 32) sgq[threadIdx.x] = g_gq[b * 32 + threadIdx.x];
  __syncthreads();
  int n = (blockIdx.x % kBPB) * kTPB + threadIdx.x;
  float vals[40];
#pragma unroll
  for (int k = 0; k < 40; k++) vals[k] = 0.f;
  if (n < kN) {
    const float* xp = g_x + (size_t)(b * kN + n) * 16;
    float x[16], y[16];
#pragma unroll
    for (int d = 0; d < 16; d += 4) {
      float4 t = *reinterpret_cast<const float4*>(xp + d);
      x[d] = t.x; x[d+1] = t.y; x[d+2] = t.z; x[d+3] = t.w;
    }
    ln16(x, cP.ln1g, cP.ln1b, y);
    u64 acc[16];
#pragma unroll
    for (int c = 0; c < 16; c++) acc[c] = 0ull;
#pragma unroll
    for (int d = 0; d < 16; d++) {
      u64 yd = pack2(y[d], y[d]);
#pragma unroll
      for (int c = 0; c < 16; c++)
        acc[c] = fma2(ldc2(&cP.Wqkv[d * 96 + 32 + 2 * c]), yd, acc[c]);
    }
    float kk[32];
#pragma unroll
    for (int c = 0; c < 16; c++) unpack2(acc[c], kk[2*c], kk[2*c+1]);
    float c0, s0, c1, s1; rot_cs(n, c0, s0, c1, s1);
#pragma unroll
    for (int h = 0; h < 8; h++) {
      float k0 = kk[4*h], k1 = kk[4*h+1], k2v = kk[4*h+2], k3 = kk[4*h+3];
      float p0 = k0*sgq[4*h+0] + k1*sgq[4*h+1];
      float p1 = k2v*sgq[4*h+2] + k3*sgq[4*h+3];
      float lg = (p0*cP.wk[0] + p1*cP.wk[1]) * kScale;
      float e = expf(lg);
      float r0 = k0*c0 - k1*s0, r1 = k1*c0 + k0*s0;
      float r2 = k2v*c1 - k3*s1, r3 = k3*c1 + k2v*s1;
      vals[h*5+0] = e;
      vals[h*5+1] = e*r0; vals[h*5+2] = e*r1;
      vals[h*5+3] = e*r2; vals[h*5+4] = e*r3;
    }
  }
  reduce40(vals, g_partK + (size_t)blockIdx.x * 40);
}

// ---------------- stage C: attention out + FF ----------------
__global__ void __launch_bounds__(kTPB) stageC_kernel(float* __restrict__ out, int last) {
  __shared__ float sgk[32];
  int b = blockIdx.x / kBPB;
  if (threadIdx.x < 32) sgk[threadIdx.x] = g_gk[b * 32 + threadIdx.x];
  __syncthreads();
  int n = (blockIdx.x % kBPB) * kTPB + threadIdx.x;
  if (n >= kN) return;

  float* xp = g_x + (size_t)(b * kN + n) * 16;
  float x[16], y[16];
#pragma unroll
  for (int d = 0; d < 16; d += 4) {
    float4 t = *reinterpret_cast<const float4*>(xp + d);
    x[d] = t.x; x[d+1] = t.y; x[d+2] = t.z; x[d+3] = t.w;
  }
  ln16(x, cP.ln1g, cP.ln1b, y);

  // q and v (cols 0..31 and 64..95), packed pairwise
  u64 aq[16], av[16];
#pragma unroll
  for (int c = 0; c < 16; c++) { aq[c] = 0ull; av[c] = 0ull; }
#pragma unroll
  for (int d = 0; d < 16; d++) {
    u64 yd = pack2(y[d], y[d]);
#pragma unroll
    for (int c = 0; c < 16; c++) {
      aq[c] = fma2(ldc2(&cP.Wqkv[d * 96 + 2 * c]), yd, aq[c]);
      av[c] = fma2(ldc2(&cP.Wqkv[d * 96 + 64 + 2 * c]), yd, av[c]);
    }
  }
  float q[32], v[32];
#pragma unroll
  for (int c = 0; c < 16; c++) { unpack2(aq[c], q[2*c], q[2*c+1]); unpack2(av[c], v[2*c], v[2*c+1]); }

  // r = u @ W_r + b_r + q
  float r[32];
#pragma unroll
  for (int h = 0; h < 8; h++) {
    float u0 = v[4*h+0]*sgk[4*h+0] + v[4*h+1]*sgk[4*h+1];
    float u1 = v[4*h+2]*sgk[4*h+2] + v[4*h+3]*sgk[4*h+3];
#pragma unroll
    for (int d = 0; d < 4; d++)
      r[4*h+d] = fmaf(u0, cP.Wr[d], fmaf(u1, cP.Wr[4+d], cP.br[d])) + q[4*h+d];
  }

  // x += r @ W_o + b_o
  u64 ao[8];
#pragma unroll
  for (int d2 = 0; d2 < 8; d2++) ao[d2] = ldc2(&cP.bo[2 * d2]);
#pragma unroll
  for (int c = 0; c < 32; c++) {
    u64 rc2 = pack2(r[c], r[c]);
#pragma unroll
    for (int d2 = 0; d2 < 8; d2++)
      ao[d2] = fma2(ldc2(&cP.Wo[c * 16 + 2 * d2]), rc2, ao[d2]);
  }
#pragma unroll
  for (int d2 = 0; d2 < 8; d2++) {
    float a0, a1; unpack2(ao[d2], a0, a1);
    x[2*d2] += a0; x[2*d2+1] += a1;
  }

  // FF block
  float y2[16];
  ln16(x, cP.ln2g, cP.ln2b, y2);
  u64 hh[32];
#pragma unroll
  for (int j2 = 0; j2 < 32; j2++) hh[j2] = ldc2(&cP.B1[2 * j2]);
#pragma unroll
  for (int d = 0; d < 16; d++) {
    u64 yd = pack2(y2[d], y2[d]);
#pragma unroll
    for (int j2 = 0; j2 < 32; j2++)
      hh[j2] = fma2(ldc2(&cP.W1[d * 64 + 2 * j2]), yd, hh[j2]);
  }
  u64 a2[8];
#pragma unroll
  for (int d2 = 0; d2 < 8; d2++) a2[d2] = ldc2(&cP.B2[2 * d2]);
#pragma unroll
  for (int j2 = 0; j2 < 32; j2++) {
    float p0, p1; unpack2(hh[j2], p0, p1);
    float h0 = 0.5f * p0 * (1.f + erff(p0 * 0.7071067811865475f));
    float h1 = 0.5f * p1 * (1.f + erff(p1 * 0.7071067811865475f));
    u64 h02 = pack2(h0, h0);
#pragma unroll
    for (int d2 = 0; d2 < 8; d2++)
      a2[d2] = fma2(ldc2(&cP.W2[(2*j2) * 16 + 2 * d2]), h02, a2[d2]);
    u64 h12 = pack2(h1, h1);
#pragma unroll
    for (int d2 = 0; d2 < 8; d2++)
      a2[d2] = fma2(ldc2(&cP.W2[(2*j2+1) * 16 + 2 * d2]), h12, a2[d2]);
  }
#pragma unroll
  for (int d2 = 0; d2 < 8; d2++) {
    float a0, a1; unpack2(a2[d2], a0, a1);
    x[2*d2] += a0; x[2*d2+1] += a1;
  }

  if (last) {
    float o = cbout[0];
#pragma unroll
    for (int d = 0; d < 16; d++) o = fmaf(x[d], cWout[d], o);
    out[(size_t)b * kN + n] = o;
  } else {
#pragma unroll
    for (int d = 0; d < 16; d += 4)
      *reinterpret_cast<float4*>(xp + d) = make_float4(x[d], x[d+1], x[d+2], x[d+3]);
  }
}

// ---------------- host launcher ----------------
extern "C" void kernel_launch(void* const* d_in, const int* in_sizes, int n_in,
                              void* d_out, int out_size) {
  (void)in_sizes; (void)n_in; (void)out_size;
  const float* corr  = (const float*)d_in[0];
  const float* W_emb = (const float*)d_in[1];
  const float* b_emb = (const float*)d_in[2];
  const float* ln1_g = (const float*)d_in[3];
  const float* ln1_b = (const float*)d_in[4];
  const float* W_qkv = (const float*)d_in[5];
  const float* w_qlog= (const float*)d_in[6];
  const float* w_klog= (const float*)d_in[7];
  const float* W_r   = (const float*)d_in[8];
  const float* b_r   = (const float*)d_in[9];
  const float* W_o   = (const float*)d_in[10];
  const float* b_o   = (const float*)d_in[11];
  const float* ln2_g = (const float*)d_in[12];
  const float* ln2_b = (const float*)d_in[13];
  const float* W_ff1 = (const float*)d_in[14];
  const float* b_ff1 = (const float*)d_in[15];
  const float* W_ff2 = (const float*)d_in[16];
  const float* b_ff2 = (const float*)d_in[17];
  const float* W_out = (const float*)d_in[18];
  const float* b_out = (const float*)d_in[19];
  float* out = (float*)d_out;

  cudaMemcpyToSymbolAsync(cWemb, W_emb, kBot * 16 * sizeof(float), 0,
                          cudaMemcpyDeviceToDevice, 0);
  cudaMemcpyToSymbolAsync(cbemb, b_emb, 16 * sizeof(float), 0,
                          cudaMemcpyDeviceToDevice, 0);
  cudaMemcpyToSymbolAsync(cWout, W_out, 16 * sizeof(float), 0,
                          cudaMemcpyDeviceToDevice, 0);
  cudaMemcpyToSymbolAsync(cbout, b_out, sizeof(float), 0,
                          cudaMemcpyDeviceToDevice, 0);

  gather_kernel<<<kL, kTPB>>>(W_qkv, ln1_g, ln1_b, w_qlog, w_klog, W_r, b_r,
                              W_o, b_o, ln2_g, ln2_b, W_ff1, b_ff1, W_ff2, b_ff2);
  embed_kernel<<<kGrid, kTPB>>>(corr);

  void* stagePtr = nullptr;
  cudaGetSymbolAddress(&stagePtr, g_stage);

  for (int i = 0; i < kL; i++) {
    cudaMemcpyToSymbolAsync(cP,
        (const char*)stagePtr + (size_t)i * kStride * sizeof(float),
        sizeof(CParams), 0, cudaMemcpyDeviceToDevice, 0);
    stageA_kernel<<<kGrid, kTPB>>>();
    finalizeQ_kernel<<<kB, 64>>>();
    stageB_kernel<<<kGrid, kTPB>>>();
    finalizeK_kernel<<<kB, 64>>>();
    stageC_kernel<<<kGrid, kTPB>>>(out, (i == kL - 1) ? 1 : 0);
  }
}

// round 5
// speedup vs baseline: 1.5281x; 1.0947x over previous
#include <cuda_runtime.h>
#include <math.h>

// ---------------- problem constants ----------------
namespace {
constexpr int kN   = 50625;          // SIDE^4
constexpr int kB   = 16;             // batch
constexpr int kBot = 26;
constexpr int kL   = 6;
constexpr int kTPB = 256;
constexpr int kBPB = (kN + kTPB - 1) / kTPB;   // 198 blocks per batch
constexpr int kGrid = kB * kBPB;               // 3168
constexpr float kScale = 0.5f;                 // DH^-0.5
}

typedef unsigned long long u64;

// ---------------- parameter banks ----------------
struct alignas(16) CParams {
  float Wqkv[1536];                  // (16,96) natural [d][96]
  float Wo[512];                     // (32,16) natural [c][16]
  float W1[1024];                    // (16,64) natural [d][64]
  float W2[1024];                    // (64,16) natural [j][16]
  float ln1g[16], ln1b[16], ln2g[16], ln2b[16];
  float wk[2], pad0[2];
  float Wr[8], br[4];
  float bo[16], B1[64], B2[16];
  // next-layer stage-A params (layer i+1), staged by gather
  float nLn1g[16], nLn1b[16];
  float nWqlog[4], pad1[4];
  float nWq[512];                    // [d][32] q columns of layer i+1
};
struct alignas(16) CA0 {             // layer-0 stage-A params (for embed fusion)
  float ln1g[16], ln1b[16], wq[4], pad[4];
  float Wq[512];                     // [d][32]
};
struct alignas(16) CGlob {
  float Wemb[kBot * 16];             // [c][16]
  float bemb[16], Wout[16], bout[4], pad[4];
};

__constant__ CParams cP;
__constant__ CA0 cA;
__constant__ CGlob cG;

// ---------------- scratch (device globals; no allocation) ----------------
__device__ float g_x[(size_t)kB * kN * 16];
__device__ float g_partQ[kGrid * 40];
__device__ float g_partK[kGrid * 40];
__device__ float g_gq[kB * 32];
__device__ float g_gk[kB * 32];
__device__ CParams g_banks[kL];
__device__ CA0 g_a0s;
__device__ CGlob g_gls;

// ---------------- packed f32x2 helpers ----------------
__device__ __forceinline__ u64 pack2(float lo, float hi) {
  u64 r; asm("mov.b64 %0,{%1,%2};" : "=l"(r) : "f"(lo), "f"(hi)); return r;
}
__device__ __forceinline__ void unpack2(u64 v, float& lo, float& hi) {
  asm("mov.b64 {%0,%1},%2;" : "=f"(lo), "=f"(hi) : "l"(v));
}
__device__ __forceinline__ u64 fma2(u64 a, u64 b, u64 c) {
  u64 d; asm("fma.rn.f32x2 %0,%1,%2,%3;" : "=l"(d) : "l"(a), "l"(b), "l"(c)); return d;
}
// 16-byte constant load -> two packed f32x2 operands (one LDCU.128)
__device__ __forceinline__ void ldc4(const float* p, u64& lo, u64& hi) {
  ulonglong2 v = *reinterpret_cast<const ulonglong2*>(p);
  lo = v.x; hi = v.y;
}
__device__ __forceinline__ u64 ldc2(const float* p) {
  return *reinterpret_cast<const u64*>(p);
}

// ---------------- scalar helpers ----------------
__device__ __forceinline__ void ln16(const float* x, const float* g,
                                     const float* bb, float* y) {
  float m = 0.f;
#pragma unroll
  for (int d = 0; d < 16; d++) m += x[d];
  m *= (1.f / 16.f);
  float v = 0.f;
#pragma unroll
  for (int d = 0; d < 16; d++) { float t = x[d] - m; v = fmaf(t, t, v); }
  v *= (1.f / 16.f);
  float r = rsqrtf(v + 1e-5f);
#pragma unroll
  for (int d = 0; d < 16; d++) y[d] = (x[d] - m) * r * g[d] + bb[d];
}

__device__ __forceinline__ void rot_cs(int n, float& c0, float& s0,
                                       float& c1, float& s1) {
  float nf = (float)n;
  float p0 = nf * 3.14159265358979323846f;
  float p1 = nf * 15.70796326794896619231f;
  double d0 = (double)p0 - (double)n * 3.14159265358979323846;
  double d1 = (double)p1 - (double)n * 15.70796326794896619231;
  float e0 = (float)d0, e1 = (float)d1;
  float sgn = (n & 1) ? -1.f : 1.f;
  c0 = sgn * (1.f - 0.5f * e0 * e0);
  s0 = sgn * e0 * (1.f - 0.1666666667f * e0 * e0);
  c1 = sgn * (1.f - 0.5f * e1 * e1);
  s1 = sgn * e1 * (1.f - 0.1666666667f * e1 * e1);
}

// stage-A statistics: LN1 -> q (32 cols) -> rotary + q-logit softmax partials.
// ALL threads of the block must call this (contains __syncthreads).
__device__ __forceinline__ void qstats_reduce(
    const float* x, bool active, int n,
    const float* lg, const float* lb, const float* Wq, const float* wql,
    float* partOut) {
  __shared__ float s_red[8][40];
  float y[16];
  ln16(x, lg, lb, y);
  float c0, s0, c1, s1; rot_cs(n, c0, s0, c1, s1);
  int lane = threadIdx.x & 31, w = threadIdx.x >> 5;
#pragma unroll
  for (int hp = 0; hp < 2; hp++) {
    u64 a[8];
#pragma unroll
    for (int m = 0; m < 8; m++) a[m] = 0ull;
#pragma unroll
    for (int d = 0; d < 16; d++) {
      u64 yd = pack2(y[d], y[d]);
      const float* row = &Wq[d * 32 + hp * 16];
#pragma unroll
      for (int h2 = 0; h2 < 4; h2++) {
        u64 w0, w1; ldc4(row + 4 * h2, w0, w1);
        a[2*h2]   = fma2(w0, yd, a[2*h2]);
        a[2*h2+1] = fma2(w1, yd, a[2*h2+1]);
      }
    }
#pragma unroll
    for (int h2 = 0; h2 < 4; h2++) {
      int h = hp * 4 + h2;
      float q0, q1, q2, q3;
      unpack2(a[2*h2], q0, q1); unpack2(a[2*h2+1], q2, q3);
      float lgt = (q0*wql[0] + q1*wql[1] + q2*wql[2] + q3*wql[3]) * kScale;
      float e = active ? __expf(lgt) : 0.f;
      float vv[5];
      vv[0] = e;
      vv[1] = e * (q0*c0 - q1*s0); vv[2] = e * (q1*c0 + q0*s0);
      vv[3] = e * (q2*c1 - q3*s1); vv[4] = e * (q3*c1 + q2*s1);
#pragma unroll
      for (int j = 0; j < 5; j++) {
        float v = vv[j];
        v += __shfl_down_sync(0xffffffffu, v, 16);
        v += __shfl_down_sync(0xffffffffu, v, 8);
        v += __shfl_down_sync(0xffffffffu, v, 4);
        v += __shfl_down_sync(0xffffffffu, v, 2);
        v += __shfl_down_sync(0xffffffffu, v, 1);
        if (lane == 0) s_red[w][h*5+j] = v;
      }
    }
  }
  __syncthreads();
  if (threadIdx.x < 40) {
    float s = 0.f;
#pragma unroll
    for (int w2 = 0; w2 < 8; w2++) s += s_red[w2][threadIdx.x];
    partOut[threadIdx.x] = s;
  }
}

// ---------------- gather: stage all params into device structs ----------------
__global__ void gather_kernel(
    const float* __restrict__ Wqkv, const float* __restrict__ ln1g,
    const float* __restrict__ ln1b, const float* __restrict__ wq,
    const float* __restrict__ wk, const float* __restrict__ Wr,
    const float* __restrict__ br, const float* __restrict__ Wo,
    const float* __restrict__ bo, const float* __restrict__ ln2g,
    const float* __restrict__ ln2b, const float* __restrict__ W1,
    const float* __restrict__ b1, const float* __restrict__ W2,
    const float* __restrict__ b2, const float* __restrict__ Wemb,
    const float* __restrict__ bemb, const float* __restrict__ Wout,
    const float* __restrict__ bout) {
  int i = blockIdx.x;
  int t = threadIdx.x;
  if (i < kL) {
    CParams* s = &g_banks[i];
    for (int k = t; k < 1536; k += kTPB) s->Wqkv[k] = Wqkv[i*1536 + k];
    for (int k = t; k < 512;  k += kTPB) s->Wo[k]  = Wo[i*512 + k];
    for (int k = t; k < 1024; k += kTPB) s->W1[k]  = W1[i*1024 + k];
    for (int k = t; k < 1024; k += kTPB) s->W2[k]  = W2[i*1024 + k];
    int jn = (i + 1 < kL) ? i + 1 : i;
    for (int k = t; k < 512; k += kTPB) {
      int d = k >> 5, c = k & 31;
      s->nWq[k] = Wqkv[jn*1536 + d*96 + c];
    }
    if (t < 16) {
      s->ln1g[t] = ln1g[i*16+t]; s->ln1b[t] = ln1b[i*16+t];
      s->ln2g[t] = ln2g[i*16+t]; s->ln2b[t] = ln2b[i*16+t];
      s->bo[t] = bo[i*16+t]; s->B2[t] = b2[i*16+t];
      s->nLn1g[t] = ln1g[jn*16+t]; s->nLn1b[t] = ln1b[jn*16+t];
    }
    if (t < 64) s->B1[t] = b1[i*64+t];
    if (t < 8)  s->Wr[t] = Wr[i*8+t];
    if (t < 4)  { s->br[t] = br[i*4+t]; s->nWqlog[t] = wq[jn*4+t]; }
    if (t < 2)  s->wk[t] = wk[i*2+t];
  } else {
    for (int k = t; k < 512; k += kTPB) {
      int d = k >> 5, c = k & 31;
      g_a0s.Wq[k] = Wqkv[d*96 + c];
    }
    if (t < 16) { g_a0s.ln1g[t] = ln1g[t]; g_a0s.ln1b[t] = ln1b[t]; }
    if (t < 4)  g_a0s.wq[t] = wq[t];
    for (int k = t; k < kBot*16; k += kTPB) g_gls.Wemb[k] = Wemb[k];
    if (t < 16) { g_gls.bemb[t] = bemb[t]; g_gls.Wout[t] = Wout[t]; }
    if (t == 0) g_gls.bout[0] = bout[0];
  }
}

// ---------------- fused embed + stage-A(layer 0) ----------------
__global__ void __launch_bounds__(kTPB) fusedEmbedA_kernel(const float* __restrict__ corr) {
  int b = blockIdx.x / kBPB;
  int n = (blockIdx.x % kBPB) * kTPB + threadIdx.x;
  bool active = n < kN;
  float x[16];
  if (active) {
    u64 acc[8];
#pragma unroll
    for (int m = 0; m < 4; m++) ldc4(&cG.bemb[4*m], acc[2*m], acc[2*m+1]);
    const float* cp = corr + (size_t)b * kBot * kN + n;
#pragma unroll 13
    for (int c = 0; c < kBot; c++) {
      float v = fmaxf(cp[(size_t)c * kN], 0.f);
      u64 v2 = pack2(v, v);
#pragma unroll
      for (int m = 0; m < 4; m++) {
        u64 w0, w1; ldc4(&cG.Wemb[c*16 + 4*m], w0, w1);
        acc[2*m]   = fma2(w0, v2, acc[2*m]);
        acc[2*m+1] = fma2(w1, v2, acc[2*m+1]);
      }
    }
    float* xp = g_x + (size_t)(b * kN + n) * 16;
#pragma unroll
    for (int m = 0; m < 8; m++) {
      unpack2(acc[m], x[2*m], x[2*m+1]);
      *reinterpret_cast<u64*>(xp + 2*m) = acc[m];
    }
  } else {
#pragma unroll
    for (int d = 0; d < 16; d++) x[d] = 0.f;
  }
  qstats_reduce(x, active, n, cA.ln1g, cA.ln1b, cA.Wq, cA.wq,
                g_partQ + (size_t)blockIdx.x * 40);
}

// ---------------- parallel finalize kernels ----------------
__global__ void finalizeQ_kernel() {
  __shared__ float s[40][6];
  int t = threadIdx.x;
  const float* pp = g_partQ + (size_t)blockIdx.x * kBPB * 40;
  if (t < 240) {
    int k = t / 6, sl = t % 6;
    float acc = 0.f;
    for (int blk = sl; blk < kBPB; blk += 6) acc += pp[blk*40 + k];
    s[k][sl] = acc;
  }
  __syncthreads();
  if (t < 40) s[t][0] = s[t][0]+s[t][1]+s[t][2]+s[t][3]+s[t][4]+s[t][5];
  __syncthreads();
  if (t < 32) {
    int h = t >> 2, d = t & 3;
    g_gq[blockIdx.x*32 + t] = s[h*5+1+d][0] / s[h*5][0];
  }
}
__global__ void finalizeK_kernel() {
  __shared__ float s[40][6];
  int t = threadIdx.x;
  const float* pp = g_partK + (size_t)blockIdx.x * kBPB * 40;
  if (t < 240) {
    int k = t / 6, sl = t % 6;
    float acc = 0.f;
    for (int blk = sl; blk < kBPB; blk += 6) acc += pp[blk*40 + k];
    s[k][sl] = acc;
  }
  __syncthreads();
  if (t < 40) s[t][0] = s[t][0]+s[t][1]+s[t][2]+s[t][3]+s[t][4]+s[t][5];
  __syncthreads();
  if (t < 32) {
    int h = t >> 2, d = t & 3;
    g_gk[blockIdx.x*32 + t] = s[h*5+1+d][0] / s[h*5][0];
  }
}

// ---------------- stage B: k stats ----------------
__global__ void __launch_bounds__(kTPB) stageB_kernel() {
  __shared__ float sgq[32];
  __shared__ float s_red[8][40];
  int b = blockIdx.x / kBPB;
  if (threadIdx.x < 32) sgq[threadIdx.x] = g_gq[b*32 + threadIdx.x];
  __syncthreads();
  int n = (blockIdx.x % kBPB) * kTPB + threadIdx.x;
  bool active = n < kN;
  float x[16];
  if (active) {
    const float* xp = g_x + (size_t)(b * kN + n) * 16;
#pragma unroll
    for (int d = 0; d < 16; d += 4) {
      float4 t4 = *reinterpret_cast<const float4*>(xp + d);
      x[d] = t4.x; x[d+1] = t4.y; x[d+2] = t4.z; x[d+3] = t4.w;
    }
  } else {
#pragma unroll
    for (int d = 0; d < 16; d++) x[d] = 0.f;
  }
  float y[16];
  ln16(x, cP.ln1g, cP.ln1b, y);
  float c0, s0, c1, s1; rot_cs(n, c0, s0, c1, s1);
  int lane = threadIdx.x & 31, w = threadIdx.x >> 5;
#pragma unroll
  for (int hp = 0; hp < 2; hp++) {
    u64 a[8];
#pragma unroll
    for (int m = 0; m < 8; m++) a[m] = 0ull;
#pragma unroll
    for (int d = 0; d < 16; d++) {
      u64 yd = pack2(y[d], y[d]);
      const float* row = &cP.Wqkv[d*96 + 32 + hp*16];
#pragma unroll
      for (int h2 = 0; h2 < 4; h2++) {
        u64 w0, w1; ldc4(row + 4*h2, w0, w1);
        a[2*h2]   = fma2(w0, yd, a[2*h2]);
        a[2*h2+1] = fma2(w1, yd, a[2*h2+1]);
      }
    }
#pragma unroll
    for (int h2 = 0; h2 < 4; h2++) {
      int h = hp * 4 + h2;
      float k0, k1, k2v, k3;
      unpack2(a[2*h2], k0, k1); unpack2(a[2*h2+1], k2v, k3);
      float p0 = k0*sgq[4*h+0] + k1*sgq[4*h+1];
      float p1 = k2v*sgq[4*h+2] + k3*sgq[4*h+3];
      float lgt = (p0*cP.wk[0] + p1*cP.wk[1]) * kScale;
      float e = active ? __expf(lgt) : 0.f;
      float vv[5];
      vv[0] = e;
      vv[1] = e * (k0*c0 - k1*s0); vv[2] = e * (k1*c0 + k0*s0);
      vv[3] = e * (k2v*c1 - k3*s1); vv[4] = e * (k3*c1 + k2v*s1);
#pragma unroll
      for (int j = 0; j < 5; j++) {
        float v = vv[j];
        v += __shfl_down_sync(0xffffffffu, v, 16);
        v += __shfl_down_sync(0xffffffffu, v, 8);
        v += __shfl_down_sync(0xffffffffu, v, 4);
        v += __shfl_down_sync(0xffffffffu, v, 2);
        v += __shfl_down_sync(0xffffffffu, v, 1);
        if (lane == 0) s_red[w][h*5+j] = v;
      }
    }
  }
  __syncthreads();
  if (threadIdx.x < 40) {
    float s = 0.f;
#pragma unroll
    for (int w2 = 0; w2 < 8; w2++) s += s_red[w2][threadIdx.x];
    g_partK[(size_t)blockIdx.x * 40 + threadIdx.x] = s;
  }
}

// ---------------- fused stage C + stage-A(next layer) ----------------
__global__ void __launch_bounds__(kTPB) fusedCA_kernel(float* __restrict__ out,
                                                       int last, int do_stats) {
  __shared__ float sgk[32];
  int b = blockIdx.x / kBPB;
  if (threadIdx.x < 32) sgk[threadIdx.x] = g_gk[b*32 + threadIdx.x];
  __syncthreads();
  int n = (blockIdx.x % kBPB) * kTPB + threadIdx.x;
  bool active = n < kN;
  float* xp = g_x + (size_t)(b * kN + n) * 16;
  float x[16];
  if (active) {
#pragma unroll
    for (int d = 0; d < 16; d += 4) {
      float4 t4 = *reinterpret_cast<const float4*>(xp + d);
      x[d] = t4.x; x[d+1] = t4.y; x[d+2] = t4.z; x[d+3] = t4.w;
    }
  } else {
#pragma unroll
    for (int d = 0; d < 16; d++) x[d] = 0.f;
  }
  float y[16];
  ln16(x, cP.ln1g, cP.ln1b, y);

  // attention: q,v in 4-head passes; accumulate W_o projection on the fly
  u64 ao[8];
#pragma unroll
  for (int m = 0; m < 4; m++) ldc4(&cP.bo[4*m], ao[2*m], ao[2*m+1]);
#pragma unroll
  for (int hp = 0; hp < 2; hp++) {
    u64 aq[8], av[8];
#pragma unroll
    for (int m = 0; m < 8; m++) { aq[m] = 0ull; av[m] = 0ull; }
#pragma unroll
    for (int d = 0; d < 16; d++) {
      u64 yd = pack2(y[d], y[d]);
      const float* row = &cP.Wqkv[d*96 + hp*16];
#pragma unroll
      for (int h2 = 0; h2 < 4; h2++) {
        u64 w0, w1; ldc4(row + 4*h2, w0, w1);
        aq[2*h2]   = fma2(w0, yd, aq[2*h2]);
        aq[2*h2+1] = fma2(w1, yd, aq[2*h2+1]);
        u64 v0, v1; ldc4(row + 64 + 4*h2, v0, v1);
        av[2*h2]   = fma2(v0, yd, av[2*h2]);
        av[2*h2+1] = fma2(v1, yd, av[2*h2+1]);
      }
    }
#pragma unroll
    for (int h2 = 0; h2 < 4; h2++) {
      int h = hp * 4 + h2;
      float q0, q1, q2, q3, v0, v1, v2, v3;
      unpack2(aq[2*h2], q0, q1); unpack2(aq[2*h2+1], q2, q3);
      unpack2(av[2*h2], v0, v1); unpack2(av[2*h2+1], v2, v3);
      float u0 = v0*sgk[4*h+0] + v1*sgk[4*h+1];
      float u1 = v2*sgk[4*h+2] + v3*sgk[4*h+3];
      float rr[4];
      rr[0] = fmaf(u0, cP.Wr[0], fmaf(u1, cP.Wr[4], cP.br[0])) + q0;
      rr[1] = fmaf(u0, cP.Wr[1], fmaf(u1, cP.Wr[5], cP.br[1])) + q1;
      rr[2] = fmaf(u0, cP.Wr[2], fmaf(u1, cP.Wr[6], cP.br[2])) + q2;
      rr[3] = fmaf(u0, cP.Wr[3], fmaf(u1, cP.Wr[7], cP.br[3])) + q3;
#pragma unroll
      for (int j = 0; j < 4; j++) {
        u64 rc = pack2(rr[j], rr[j]);
        const float* wrow = &cP.Wo[(4*h+j)*16];
#pragma unroll
        for (int m = 0; m < 4; m++) {
          u64 w0, w1; ldc4(wrow + 4*m, w0, w1);
          ao[2*m]   = fma2(w0, rc, ao[2*m]);
          ao[2*m+1] = fma2(w1, rc, ao[2*m+1]);
        }
      }
    }
  }
#pragma unroll
  for (int m = 0; m < 8; m++) {
    float a0, a1; unpack2(ao[m], a0, a1);
    x[2*m] += a0; x[2*m+1] += a1;
  }

  // FF block, 2 chunks of 32 hidden units
  float y2[16];
  ln16(x, cP.ln2g, cP.ln2b, y2);
  u64 a2[8];
#pragma unroll
  for (int m = 0; m < 4; m++) ldc4(&cP.B2[4*m], a2[2*m], a2[2*m+1]);
#pragma unroll
  for (int jc = 0; jc < 2; jc++) {
    u64 hh[16];
#pragma unroll
    for (int m = 0; m < 8; m++) ldc4(&cP.B1[jc*32 + 4*m], hh[2*m], hh[2*m+1]);
#pragma unroll
    for (int d = 0; d < 16; d++) {
      u64 yd = pack2(y2[d], y2[d]);
      const float* row = &cP.W1[d*64 + jc*32];
#pragma unroll
      for (int m = 0; m < 8; m++) {
        u64 w0, w1; ldc4(row + 4*m, w0, w1);
        hh[2*m]   = fma2(w0, yd, hh[2*m]);
        hh[2*m+1] = fma2(w1, yd, hh[2*m+1]);
      }
    }
#pragma unroll
    for (int m = 0; m < 16; m++) {
      float p0, p1; unpack2(hh[m], p0, p1);
      float g0 = 0.5f * p0 * (1.f + erff(p0 * 0.7071067811865475f));
      float g1 = 0.5f * p1 * (1.f + erff(p1 * 0.7071067811865475f));
      int j0 = jc*32 + 2*m;
      u64 h0 = pack2(g0, g0);
      const float* w2r = &cP.W2[j0*16];
#pragma unroll
      for (int mm = 0; mm < 4; mm++) {
        u64 w0, w1; ldc4(w2r + 4*mm, w0, w1);
        a2[2*mm]   = fma2(w0, h0, a2[2*mm]);
        a2[2*mm+1] = fma2(w1, h0, a2[2*mm+1]);
      }
      u64 h1 = pack2(g1, g1);
      w2r += 16;
#pragma unroll
      for (int mm = 0; mm < 4; mm++) {
        u64 w0, w1; ldc4(w2r + 4*mm, w0, w1);
        a2[2*mm]   = fma2(w0, h1, a2[2*mm]);
        a2[2*mm+1] = fma2(w1, h1, a2[2*mm+1]);
      }
    }
  }
#pragma unroll
  for (int m = 0; m < 8; m++) {
    float a0, a1; unpack2(a2[m], a0, a1);
    x[2*m] += a0; x[2*m+1] += a1;
  }

  if (last) {
    if (active) {
      float o = cG.bout[0];
#pragma unroll
      for (int d = 0; d < 16; d++) o = fmaf(x[d], cG.Wout[d], o);
      out[(size_t)b * kN + n] = o;
    }
  } else {
    if (active) {
#pragma unroll
      for (int d = 0; d < 16; d += 4)
        *reinterpret_cast<float4*>(xp + d) =
            make_float4(x[d], x[d+1], x[d+2], x[d+3]);
    }
  }
  if (do_stats) {
    qstats_reduce(x, active, n, cP.nLn1g, cP.nLn1b, cP.nWq, cP.nWqlog,
                  g_partQ + (size_t)blockIdx.x * 40);
  }
}

// ---------------- host launcher ----------------
extern "C" void kernel_launch(void* const* d_in, const int* in_sizes, int n_in,
                              void* d_out, int out_size) {
  (void)in_sizes; (void)n_in; (void)out_size;
  const float* corr  = (const float*)d_in[0];
  const float* W_emb = (const float*)d_in[1];
  const float* b_emb = (const float*)d_in[2];
  const float* ln1_g = (const float*)d_in[3];
  const float* ln1_b = (const float*)d_in[4];
  const float* W_qkv = (const float*)d_in[5];
  const float* w_qlog= (const float*)d_in[6];
  const float* w_klog= (const float*)d_in[7];
  const float* W_r   = (const float*)d_in[8];
  const float* b_r   = (const float*)d_in[9];
  const float* W_o   = (const float*)d_in[10];
  const float* b_o   = (const float*)d_in[11];
  const float* ln2_g = (const float*)d_in[12];
  const float* ln2_b = (const float*)d_in[13];
  const float* W_ff1 = (const float*)d_in[14];
  const float* b_ff1 = (const float*)d_in[15];
  const float* W_ff2 = (const float*)d_in[16];
  const float* b_ff2 = (const float*)d_in[17];
  const float* W_out = (const float*)d_in[18];
  const float* b_out = (const float*)d_in[19];
  float* out = (float*)d_out;

  gather_kernel<<<kL + 1, kTPB>>>(W_qkv, ln1_g, ln1_b, w_qlog, w_klog, W_r,
                                  b_r, W_o, b_o, ln2_g, ln2_b, W_ff1, b_ff1,
                                  W_ff2, b_ff2, W_emb, b_emb, W_out, b_out);

  void *pBanks = nullptr, *pA0 = nullptr, *pGl = nullptr;
  cudaGetSymbolAddress(&pBanks, g_banks);
  cudaGetSymbolAddress(&pA0, g_a0s);
  cudaGetSymbolAddress(&pGl, g_gls);

  cudaMemcpyToSymbolAsync(cG, pGl, sizeof(CGlob), 0, cudaMemcpyDeviceToDevice, 0);
  cudaMemcpyToSymbolAsync(cA, pA0, sizeof(CA0), 0, cudaMemcpyDeviceToDevice, 0);
  cudaMemcpyToSymbolAsync(cP, pBanks, sizeof(CParams), 0,
                          cudaMemcpyDeviceToDevice, 0);

  fusedEmbedA_kernel<<<kGrid, kTPB>>>(corr);

  for (int i = 0; i < kL; i++) {
    finalizeQ_kernel<<<kB, 256>>>();
    stageB_kernel<<<kGrid, kTPB>>>();
    finalizeK_kernel<<<kB, 256>>>();
    fusedCA_kernel<<<kGrid, kTPB>>>(out, (i == kL - 1) ? 1 : 0,
                                    (i < kL - 1) ? 1 : 0);
    if (i + 1 < kL) {
      cudaMemcpyToSymbolAsync(
          cP, (const char*)pBanks + (size_t)(i + 1) * sizeof(CParams),
          sizeof(CParams), 0, cudaMemcpyDeviceToDevice, 0);
    }
  }
}

// round 7
// speedup vs baseline: 1.6248x; 1.0633x over previous
#include <cuda_runtime.h>
#include <math.h>

// ---------------- problem constants ----------------
namespace {
constexpr int kN   = 50625;          // SIDE^4
constexpr int kB   = 16;             // batch
constexpr int kBot = 26;
constexpr int kL   = 6;
constexpr int kTPB = 256;
constexpr int kBPB = (kN + kTPB - 1) / kTPB;   // 198 blocks per batch
constexpr int kNP  = kBPB * kTPB;              // padded tokens (50688)
constexpr int kGrid = kB * kBPB;               // 3168
constexpr float kScale = 0.5f;                 // DH^-0.5
}

typedef unsigned long long u64;

// ---------------- parameter banks ----------------
struct alignas(16) CParams {
  float Wqkv[1536];                  // (16,96) natural [d][96]
  float Wo[512];                     // (32,16) natural [c][16]
  float W1[1024];                    // (16,64) natural [d][64]
  float W2[1024];                    // (64,16) natural [j][16]
  float ln1g[16], ln1b[16], ln2g[16], ln2b[16];
  float wk[2], pad0[2];
  float Wr[8], br[4];
  float bo[16], B1[64], B2[16];
  // next-layer stage-A params (layer i+1), staged by gather
  float nLn1g[16], nLn1b[16];
  float nWqlog[4], pad1[4];
  float nWq[512];                    // [d][32] q columns of layer i+1
};
struct alignas(16) CA0 {             // layer-0 stage-A params (for embed fusion)
  float ln1g[16], ln1b[16], wq[4], pad[4];
  float Wq[512];                     // [d][32]
};
struct alignas(16) CGlob {
  float Wemb[kBot * 16];             // [c][16]
  float bemb[16], Wout[16], bout[4], pad[4];
};

__constant__ CParams cP;
__constant__ CA0 cA;
__constant__ CGlob cG;

// ---------------- scratch (device globals; no allocation) ----------------
// x stored blocked-SoA: [b][blk][m(0..3)][t(0..255)] as float4
__device__ float g_x[(size_t)kB * kBPB * 4 * kTPB * 4];
__device__ float4 g_rot[kNP];
__device__ float g_partQ[kGrid * 40];
__device__ float g_partK[kGrid * 40];
__device__ float g_gq[kB * 32];
__device__ float g_gk[kB * 32];
__device__ CParams g_banks[kL];
__device__ CA0 g_a0s;
__device__ CGlob g_gls;

// ---------------- packed f32x2 helpers ----------------
__device__ __forceinline__ u64 pack2(float lo, float hi) {
  u64 r; asm("mov.b64 %0,{%1,%2};" : "=l"(r) : "f"(lo), "f"(hi)); return r;
}
__device__ __forceinline__ void unpack2(u64 v, float& lo, float& hi) {
  asm("mov.b64 {%0,%1},%2;" : "=f"(lo), "=f"(hi) : "l"(v));
}
__device__ __forceinline__ u64 fma2(u64 a, u64 b, u64 c) {
  u64 d; asm("fma.rn.f32x2 %0,%1,%2,%3;" : "=l"(d) : "l"(a), "l"(b), "l"(c)); return d;
}
// 16-byte constant load -> two packed f32x2 operands (one LDCU.128)
__device__ __forceinline__ void ldc4(const float* p, u64& lo, u64& hi) {
  ulonglong2 v = *reinterpret_cast<const ulonglong2*>(p);
  lo = v.x; hi = v.y;
}

// ---------------- scalar helpers ----------------
__device__ __forceinline__ void ln16(const float* x, const float* g,
                                     const float* bb, float* y) {
  float m = 0.f;
#pragma unroll
  for (int d = 0; d < 16; d++) m += x[d];
  m *= (1.f / 16.f);
  float v = 0.f;
#pragma unroll
  for (int d = 0; d < 16; d++) { float t = x[d] - m; v = fmaf(t, t, v); }
  v *= (1.f / 16.f);
  float r = rsqrtf(v + 1e-5f);
#pragma unroll
  for (int d = 0; d < 16; d++) y[d] = (x[d] - m) * r * g[d] + bb[d];
}

// exact-semantics rotary values (run once in prep kernel; fp64 OK there)
__device__ __forceinline__ void rot_cs(int n, float& c0, float& s0,
                                       float& c1, float& s1) {
  float nf = (float)n;
  float p0 = nf * 3.14159265358979323846f;
  float p1 = nf * 15.70796326794896619231f;
  double d0 = (double)p0 - (double)n * 3.14159265358979323846;
  double d1 = (double)p1 - (double)n * 15.70796326794896619231;
  float e0 = (float)d0, e1 = (float)d1;
  float sgn = (n & 1) ? -1.f : 1.f;
  c0 = sgn * (1.f - 0.5f * e0 * e0);
  s0 = sgn * e0 * (1.f - 0.1666666667f * e0 * e0);
  c1 = sgn * (1.f - 0.5f * e1 * e1);
  s1 = sgn * e1 * (1.f - 0.1666666667f * e1 * e1);
}

// fast exact-erf gelu: A&S 7.1.26, |abs err| <= ~3e-7
__device__ __forceinline__ float gelu_fast(float p) {
  float xs = p * 0.7071067811865475f;
  float ax = fabsf(xs);
  float t = __fdividef(1.f, fmaf(0.3275911f, ax, 1.f));
  float poly = t * fmaf(t, fmaf(t, fmaf(t, fmaf(t, 1.061405429f,
                   -1.453152027f), 1.421413741f), -0.284496736f),
                   0.254829592f);
  float e = __expf(-ax * ax);
  float er = 1.f - poly * e;
  er = copysignf(er, xs);
  return 0.5f * p * (1.f + er);
}

// block reduction of 40 per-thread floats via smem transpose (paired 64-bit)
// ALL 256 threads must call (contains __syncthreads). Deterministic.
__device__ __forceinline__ void reduce40_pairs(const float* vals, float* partOut) {
  __shared__ u64 sT[20 * 257];
  __shared__ float sS[40][12];
  int t = threadIdx.x;
#pragma unroll
  for (int p = 0; p < 20; p++)
    sT[p * 257 + t] = pack2(vals[2*p], vals[2*p+1]);
  __syncthreads();
  if (t < 240) {
    int p = t / 12, sl = t % 12;
    float s0 = 0.f, s1 = 0.f;
    const u64* row = &sT[p * 257];
#pragma unroll
    for (int i = sl; i < kTPB; i += 12) {
      float a, b; unpack2(row[i], a, b);
      s0 += a; s1 += b;
    }
    sS[2*p][sl] = s0; sS[2*p+1][sl] = s1;
  }
  __syncthreads();
  if (t < 40) {
    float s = 0.f;
#pragma unroll
    for (int j = 0; j < 12; j++) s += sS[t][j];
    partOut[t] = s;
  }
}

// x tile pointer for (batch, block)
__device__ __forceinline__ float4* xblock(int b, int blk) {
  return reinterpret_cast<float4*>(g_x) + ((size_t)(b * kBPB + blk) * 4) * kTPB;
}

// stage-A statistics: LN1 -> q (32 cols) -> rotary + q-logit softmax partials.
__device__ __forceinline__ void qstats_reduce(
    const float* x, bool active, int n,
    const float* lg, const float* lb, const float* Wq, const float* wql,
    float* partOut) {
  float y[16];
  ln16(x, lg, lb, y);
  float4 rt = g_rot[n];
  float vals[40];
#pragma unroll
  for (int hp = 0; hp < 2; hp++) {
    u64 a[8];
#pragma unroll
    for (int m = 0; m < 8; m++) a[m] = 0ull;
#pragma unroll
    for (int d = 0; d < 16; d++) {
      u64 yd = pack2(y[d], y[d]);
      const float* row = &Wq[d * 32 + hp * 16];
#pragma unroll
      for (int h2 = 0; h2 < 4; h2++) {
        u64 w0, w1; ldc4(row + 4 * h2, w0, w1);
        a[2*h2]   = fma2(w0, yd, a[2*h2]);
        a[2*h2+1] = fma2(w1, yd, a[2*h2+1]);
      }
    }
#pragma unroll
    for (int h2 = 0; h2 < 4; h2++) {
      int h = hp * 4 + h2;
      float q0, q1, q2, q3;
      unpack2(a[2*h2], q0, q1); unpack2(a[2*h2+1], q2, q3);
      float lgt = (q0*wql[0] + q1*wql[1] + q2*wql[2] + q3*wql[3]) * kScale;
      float e = active ? __expf(lgt) : 0.f;
      vals[h*5+0] = e;
      vals[h*5+1] = e * (q0*rt.x - q1*rt.y);
      vals[h*5+2] = e * (q1*rt.x + q0*rt.y);
      vals[h*5+3] = e * (q2*rt.z - q3*rt.w);
      vals[h*5+4] = e * (q3*rt.z + q2*rt.w);
    }
  }
  reduce40_pairs(vals, partOut);
}

// ---------------- prep kernels ----------------
__global__ void rotprep_kernel() {
  int n = blockIdx.x * kTPB + threadIdx.x;
  float c0, s0, c1, s1; rot_cs(n, c0, s0, c1, s1);
  g_rot[n] = make_float4(c0, s0, c1, s1);
}

__global__ void gather_kernel(
    const float* __restrict__ Wqkv, const float* __restrict__ ln1g,
    const float* __restrict__ ln1b, const float* __restrict__ wq,
    const float* __restrict__ wk, const float* __restrict__ Wr,
    const float* __restrict__ br, const float* __restrict__ Wo,
    const float* __restrict__ bo, const float* __restrict__ ln2g,
    const float* __restrict__ ln2b, const float* __restrict__ W1,
    const float* __restrict__ b1, const float* __restrict__ W2,
    const float* __restrict__ b2, const float* __restrict__ Wemb,
    const float* __restrict__ bemb, const float* __restrict__ Wout,
    const float* __restrict__ bout) {
  int i = blockIdx.x;
  int t = threadIdx.x;
  if (i < kL) {
    CParams* s = &g_banks[i];
    for (int k = t; k < 1536; k += kTPB) s->Wqkv[k] = Wqkv[i*1536 + k];
    for (int k = t; k < 512;  k += kTPB) s->Wo[k]  = Wo[i*512 + k];
    for (int k = t; k < 1024; k += kTPB) s->W1[k]  = W1[i*1024 + k];
    for (int k = t; k < 1024; k += kTPB) s->W2[k]  = W2[i*1024 + k];
    int jn = (i + 1 < kL) ? i + 1 : i;
    for (int k = t; k < 512; k += kTPB) {
      int d = k >> 5, c = k & 31;
      s->nWq[k] = Wqkv[jn*1536 + d*96 + c];
    }
    if (t < 16) {
      s->ln1g[t] = ln1g[i*16+t]; s->ln1b[t] = ln1b[i*16+t];
      s->ln2g[t] = ln2g[i*16+t]; s->ln2b[t] = ln2b[i*16+t];
      s->bo[t] = bo[i*16+t]; s->B2[t] = b2[i*16+t];
      s->nLn1g[t] = ln1g[jn*16+t]; s->nLn1b[t] = ln1b[jn*16+t];
    }
    if (t < 64) s->B1[t] = b1[i*64+t];
    if (t < 8)  s->Wr[t] = Wr[i*8+t];
    if (t < 4)  { s->br[t] = br[i*4+t]; s->nWqlog[t] = wq[jn*4+t]; }
    if (t < 2)  s->wk[t] = wk[i*2+t];
  } else {
    for (int k = t; k < 512; k += kTPB) {
      int d = k >> 5, c = k & 31;
      g_a0s.Wq[k] = Wqkv[d*96 + c];
    }
    if (t < 16) { g_a0s.ln1g[t] = ln1g[t]; g_a0s.ln1b[t] = ln1b[t]; }
    if (t < 4)  g_a0s.wq[t] = wq[t];
    for (int k = t; k < kBot*16; k += kTPB) g_gls.Wemb[k] = Wemb[k];
    if (t < 16) { g_gls.bemb[t] = bemb[t]; g_gls.Wout[t] = Wout[t]; }
    if (t == 0) g_gls.bout[0] = bout[0];
  }
}

// ---------------- fused embed + stage-A(layer 0) ----------------
__global__ void __launch_bounds__(kTPB) fusedEmbedA_kernel(const float* __restrict__ corr) {
  int b = blockIdx.x / kBPB;
  int blk = blockIdx.x % kBPB;
  int t = threadIdx.x;
  int n = blk * kTPB + t;
  bool active = n < kN;
  float x[16];
  if (active) {
    u64 acc[8];
#pragma unroll
    for (int m = 0; m < 4; m++) ldc4(&cG.bemb[4*m], acc[2*m], acc[2*m+1]);
    const float* cp = corr + (size_t)b * kBot * kN + n;
#pragma unroll 13
    for (int c = 0; c < kBot; c++) {
      float v = fmaxf(cp[(size_t)c * kN], 0.f);
      u64 v2 = pack2(v, v);
#pragma unroll
      for (int m = 0; m < 4; m++) {
        u64 w0, w1; ldc4(&cG.Wemb[c*16 + 4*m], w0, w1);
        acc[2*m]   = fma2(w0, v2, acc[2*m]);
        acc[2*m+1] = fma2(w1, v2, acc[2*m+1]);
      }
    }
#pragma unroll
    for (int m = 0; m < 8; m++) unpack2(acc[m], x[2*m], x[2*m+1]);
  } else {
#pragma unroll
    for (int d = 0; d < 16; d++) x[d] = 0.f;
  }
  float4* xb = xblock(b, blk);
#pragma unroll
  for (int m = 0; m < 4; m++)
    xb[m * kTPB + t] = make_float4(x[4*m], x[4*m+1], x[4*m+2], x[4*m+3]);
  qstats_reduce(x, active, n, cA.ln1g, cA.ln1b, cA.Wq, cA.wq,
                g_partQ + (size_t)blockIdx.x * 40);
}

// ---------------- parallel finalize kernels ----------------
__global__ void finalizeQ_kernel() {
  __shared__ float s[40][6];
  int t = threadIdx.x;
  const float* pp = g_partQ + (size_t)blockIdx.x * kBPB * 40;
  if (t < 240) {
    int k = t / 6, sl = t % 6;
    float acc = 0.f;
    for (int blk = sl; blk < kBPB; blk += 6) acc += pp[blk*40 + k];
    s[k][sl] = acc;
  }
  __syncthreads();
  if (t < 40) s[t][0] = s[t][0]+s[t][1]+s[t][2]+s[t][3]+s[t][4]+s[t][5];
  __syncthreads();
  if (t < 32) {
    int h = t >> 2, d = t & 3;
    g_gq[blockIdx.x*32 + t] = s[h*5+1+d][0] / s[h*5][0];
  }
}
__global__ void finalizeK_kernel() {
  __shared__ float s[40][6];
  int t = threadIdx.x;
  const float* pp = g_partK + (size_t)blockIdx.x * kBPB * 40;
  if (t < 240) {
    int k = t / 6, sl = t % 6;
    float acc = 0.f;
    for (int blk = sl; blk < kBPB; blk += 6) acc += pp[blk*40 + k];
    s[k][sl] = acc;
  }
  __syncthreads();
  if (t < 40) s[t][0] = s[t][0]+s[t][1]+s[t][2]+s[t][3]+s[t][4]+s[t][5];
  __syncthreads();
  if (t < 32) {
    int h = t >> 2, d = t & 3;
    g_gk[blockIdx.x*32 + t] = s[h*5+1+d][0] / s[h*5][0];
  }
}

// ---------------- stage B: k stats ----------------
__global__ void __launch_bounds__(kTPB) stageB_kernel() {
  __shared__ float sgq[32];
  int b = blockIdx.x / kBPB;
  int blk = blockIdx.x % kBPB;
  int t = threadIdx.x;
  if (t < 32) sgq[t] = g_gq[b*32 + t];
  __syncthreads();
  int n = blk * kTPB + t;
  bool active = n < kN;
  float x[16];
  const float4* xb = xblock(b, blk);
#pragma unroll
  for (int m = 0; m < 4; m++) {
    float4 t4 = xb[m * kTPB + t];
    x[4*m] = t4.x; x[4*m+1] = t4.y; x[4*m+2] = t4.z; x[4*m+3] = t4.w;
  }
  float y[16];
  ln16(x, cP.ln1g, cP.ln1b, y);
  float4 rt = g_rot[n];
  float vals[40];
#pragma unroll
  for (int hp = 0; hp < 2; hp++) {
    u64 a[8];
#pragma unroll
    for (int m = 0; m < 8; m++) a[m] = 0ull;
#pragma unroll
    for (int d = 0; d < 16; d++) {
      u64 yd = pack2(y[d], y[d]);
      const float* row = &cP.Wqkv[d*96 + 32 + hp*16];
#pragma unroll
      for (int h2 = 0; h2 < 4; h2++) {
        u64 w0, w1; ldc4(row + 4*h2, w0, w1);
        a[2*h2]   = fma2(w0, yd, a[2*h2]);
        a[2*h2+1] = fma2(w1, yd, a[2*h2+1]);
      }
    }
#pragma unroll
    for (int h2 = 0; h2 < 4; h2++) {
      int h = hp * 4 + h2;
      float k0, k1, k2v, k3;
      unpack2(a[2*h2], k0, k1); unpack2(a[2*h2+1], k2v, k3);
      float p0 = k0*sgq[4*h+0] + k1*sgq[4*h+1];
      float p1 = k2v*sgq[4*h+2] + k3*sgq[4*h+3];
      float lgt = (p0*cP.wk[0] + p1*cP.wk[1]) * kScale;
      float e = active ? __expf(lgt) : 0.f;
      vals[h*5+0] = e;
      vals[h*5+1] = e * (k0*rt.x - k1*rt.y);
      vals[h*5+2] = e * (k1*rt.x + k0*rt.y);
      vals[h*5+3] = e * (k2v*rt.z - k3*rt.w);
      vals[h*5+4] = e * (k3*rt.z + k2v*rt.w);
    }
  }
  reduce40_pairs(vals, g_partK + (size_t)blockIdx.x * 40);
}

// ---------------- fused stage C + stage-A(next layer) ----------------
__global__ void __launch_bounds__(kTPB) fusedCA_kernel(float* __restrict__ out,
                                                       int last, int do_stats) {
  __shared__ float sgk[32];
  int b = blockIdx.x / kBPB;
  int blk = blockIdx.x % kBPB;
  int t = threadIdx.x;
  if (t < 32) sgk[t] = g_gk[b*32 + t];
  __syncthreads();
  int n = blk * kTPB + t;
  bool active = n < kN;
  float4* xb = xblock(b, blk);
  float x[16];
#pragma unroll
  for (int m = 0; m < 4; m++) {
    float4 t4 = xb[m * kTPB + t];
    x[4*m] = t4.x; x[4*m+1] = t4.y; x[4*m+2] = t4.z; x[4*m+3] = t4.w;
  }
  float y[16];
  ln16(x, cP.ln1g, cP.ln1b, y);

  // attention: q,v in 4-head passes; accumulate W_o projection on the fly
  u64 ao[8];
#pragma unroll
  for (int m = 0; m < 4; m++) ldc4(&cP.bo[4*m], ao[2*m], ao[2*m+1]);
#pragma unroll
  for (int hp = 0; hp < 2; hp++) {
    u64 aq[8], av[8];
#pragma unroll
    for (int m = 0; m < 8; m++) { aq[m] = 0ull; av[m] = 0ull; }
#pragma unroll
    for (int d = 0; d < 16; d++) {
      u64 yd = pack2(y[d], y[d]);
      const float* row = &cP.Wqkv[d*96 + hp*16];
#pragma unroll
      for (int h2 = 0; h2 < 4; h2++) {
        u64 w0, w1; ldc4(row + 4*h2, w0, w1);
        aq[2*h2]   = fma2(w0, yd, aq[2*h2]);
        aq[2*h2+1] = fma2(w1, yd, aq[2*h2+1]);
        u64 v0, v1; ldc4(row + 64 + 4*h2, v0, v1);
        av[2*h2]   = fma2(v0, yd, av[2*h2]);
        av[2*h2+1] = fma2(v1, yd, av[2*h2+1]);
      }
    }
#pragma unroll
    for (int h2 = 0; h2 < 4; h2++) {
      int h = hp * 4 + h2;
      float q0, q1, q2, q3, v0, v1, v2, v3;
      unpack2(aq[2*h2], q0, q1); unpack2(aq[2*h2+1], q2, q3);
      unpack2(av[2*h2], v0, v1); unpack2(av[2*h2+1], v2, v3);
      float u0 = v0*sgk[4*h+0] + v1*sgk[4*h+1];
      float u1 = v2*sgk[4*h+2] + v3*sgk[4*h+3];
      float rr[4];
      rr[0] = fmaf(u0, cP.Wr[0], fmaf(u1, cP.Wr[4], cP.br[0])) + q0;
      rr[1] = fmaf(u0, cP.Wr[1], fmaf(u1, cP.Wr[5], cP.br[1])) + q1;
      rr[2] = fmaf(u0, cP.Wr[2], fmaf(u1, cP.Wr[6], cP.br[2])) + q2;
      rr[3] = fmaf(u0, cP.Wr[3], fmaf(u1, cP.Wr[7], cP.br[3])) + q3;
#pragma unroll
      for (int j = 0; j < 4; j++) {
        u64 rc = pack2(rr[j], rr[j]);
        const float* wrow = &cP.Wo[(4*h+j)*16];
#pragma unroll
        for (int m = 0; m < 4; m++) {
          u64 w0, w1; ldc4(wrow + 4*m, w0, w1);
          ao[2*m]   = fma2(w0, rc, ao[2*m]);
          ao[2*m+1] = fma2(w1, rc, ao[2*m+1]);
        }
      }
    }
  }
#pragma unroll
  for (int m = 0; m < 8; m++) {
    float a0, a1; unpack2(ao[m], a0, a1);
    x[2*m] += a0; x[2*m+1] += a1;
  }

  // FF block, 2 chunks of 32 hidden units
  float y2[16];
  ln16(x, cP.ln2g, cP.ln2b, y2);
  u64 a2[8];
#pragma unroll
  for (int m = 0; m < 4; m++) ldc4(&cP.B2[4*m], a2[2*m], a2[2*m+1]);
#pragma unroll
  for (int jc = 0; jc < 2; jc++) {
    u64 hh[16];
#pragma unroll
    for (int m = 0; m < 8; m++) ldc4(&cP.B1[jc*32 + 4*m], hh[2*m], hh[2*m+1]);
#pragma unroll
    for (int d = 0; d < 16; d++) {
      u64 yd = pack2(y2[d], y2[d]);
      const float* row = &cP.W1[d*64 + jc*32];
#pragma unroll
      for (int m = 0; m < 8; m++) {
        u64 w0, w1; ldc4(row + 4*m, w0, w1);
        hh[2*m]   = fma2(w0, yd, hh[2*m]);
        hh[2*m+1] = fma2(w1, yd, hh[2*m+1]);
      }
    }
#pragma unroll
    for (int m = 0; m < 16; m++) {
      float p0, p1; unpack2(hh[m], p0, p1);
      float g0 = gelu_fast(p0);
      float g1 = gelu_fast(p1);
      int j0 = jc*32 + 2*m;
      u64 h0 = pack2(g0, g0);
      const float* w2r = &cP.W2[j0*16];
#pragma unroll
      for (int mm = 0; mm < 4; mm++) {
        u64 w0, w1; ldc4(w2r + 4*mm, w0, w1);
        a2[2*mm]   = fma2(w0, h0, a2[2*mm]);
        a2[2*mm+1] = fma2(w1, h0, a2[2*mm+1]);
      }
      u64 h1 = pack2(g1, g1);
      w2r += 16;
#pragma unroll
      for (int mm = 0; mm < 4; mm++) {
        u64 w0, w1; ldc4(w2r + 4*mm, w0, w1);
        a2[2*mm]   = fma2(w0, h1, a2[2*mm]);
        a2[2*mm+1] = fma2(w1, h1, a2[2*mm+1]);
      }
    }
  }
#pragma unroll
  for (int m = 0; m < 8; m++) {
    float a0, a1; unpack2(a2[m], a0, a1);
    x[2*m] += a0; x[2*m+1] += a1;
  }

  if (last) {
    if (active) {
      float o = cG.bout[0];
#pragma unroll
      for (int d = 0; d < 16; d++) o = fmaf(x[d], cG.Wout[d], o);
      out[(size_t)b * kN + n] = o;
    }
  } else {
#pragma unroll
    for (int m = 0; m < 4; m++)
      xb[m * kTPB + t] = make_float4(x[4*m], x[4*m+1], x[4*m+2], x[4*m+3]);
  }
  if (do_stats) {
    qstats_reduce(x, active, n, cP.nLn1g, cP.nLn1b, cP.nWq, cP.nWqlog,
                  g_partQ + (size_t)blockIdx.x * 40);
  }
}

// ---------------- host launcher ----------------
extern "C" void kernel_launch(void* const* d_in, const int* in_sizes, int n_in,
                              void* d_out, int out_size) {
  (void)in_sizes; (void)n_in; (void)out_size;
  const float* corr  = (const float*)d_in[0];
  const float* W_emb = (const float*)d_in[1];
  const float* b_emb = (const float*)d_in[2];
  const float* ln1_g = (const float*)d_in[3];
  const float* ln1_b = (const float*)d_in[4];
  const float* W_qkv = (const float*)d_in[5];
  const float* w_qlog= (const float*)d_in[6];
  const float* w_klog= (const float*)d_in[7];
  const float* W_r   = (const float*)d_in[8];
  const float* b_r   = (const float*)d_in[9];
  const float* W_o   = (const float*)d_in[10];
  const float* b_o   = (const float*)d_in[11];
  const float* ln2_g = (const float*)d_in[12];
  const float* ln2_b = (const float*)d_in[13];
  const float* W_ff1 = (const float*)d_in[14];
  const float* b_ff1 = (const float*)d_in[15];
  const float* W_ff2 = (const float*)d_in[16];
  const float* b_ff2 = (const float*)d_in[17];
  const float* W_out = (const float*)d_in[18];
  const float* b_out = (const float*)d_in[19];
  float* out = (float*)d_out;

  rotprep_kernel<<<kBPB, kTPB>>>();
  gather_kernel<<<kL + 1, kTPB>>>(W_qkv, ln1_g, ln1_b, w_qlog, w_klog, W_r,
                                  b_r, W_o, b_o, ln2_g, ln2_b, W_ff1, b_ff1,
                                  W_ff2, b_ff2, W_emb, b_emb, W_out, b_out);

  void *pBanks = nullptr, *pA0 = nullptr, *pGl = nullptr;
  cudaGetSymbolAddress(&pBanks, g_banks);
  cudaGetSymbolAddress(&pA0, g_a0s);
  cudaGetSymbolAddress(&pGl, g_gls);

  cudaMemcpyToSymbolAsync(cG, pGl, sizeof(CGlob), 0, cudaMemcpyDeviceToDevice, 0);
  cudaMemcpyToSymbolAsync(cA, pA0, sizeof(CA0), 0, cudaMemcpyDeviceToDevice, 0);
  cudaMemcpyToSymbolAsync(cP, pBanks, sizeof(CParams), 0,
                          cudaMemcpyDeviceToDevice, 0);

  fusedEmbedA_kernel<<<kGrid, kTPB>>>(corr);

  for (int i = 0; i < kL; i++) {
    finalizeQ_kernel<<<kB, 256>>>();
    stageB_kernel<<<kGrid, kTPB>>>();
    finalizeK_kernel<<<kB, 256>>>();
    fusedCA_kernel<<<kGrid, kTPB>>>(out, (i == kL - 1) ? 1 : 0,
                                    (i < kL - 1) ? 1 : 0);
    if (i + 1 < kL) {
      cudaMemcpyToSymbolAsync(
          cP, (const char*)pBanks + (size_t)(i + 1) * sizeof(CParams),
          sizeof(CParams), 0, cudaMemcpyDeviceToDevice, 0);
    }
  }
}

// round 8
// speedup vs baseline: 1.6804x; 1.0342x over previous
#include <cuda_runtime.h>
#include <math.h>

// ---------------- problem constants ----------------
namespace {
constexpr int kN   = 50625;          // SIDE^4
constexpr int kB   = 16;             // batch
constexpr int kBot = 26;
constexpr int kL   = 6;
constexpr int kTPB = 256;
constexpr int kBPB = (kN + kTPB - 1) / kTPB;   // 198 blocks per batch
constexpr int kNP  = kBPB * kTPB;              // padded tokens (50688)
constexpr int kGrid = kB * kBPB;               // 3168
constexpr float kScale = 0.5f;                 // DH^-0.5
}

typedef unsigned long long u64;

// ---------------- parameter banks ----------------
struct alignas(16) CParams {
  float Wqkv[1536];                  // (16,96) natural [d][96] (k cols 32.., v cols 64..)
  float WqWo[256];                   // folded Wq@Wo  [d][16]
  float WrWo[256];                   // folded Wr@Wo  [(h*2+p)][16]
  float W1[1024];                    // (16,64) natural [d][64]
  float W2[1024];                    // (64,16) natural [j][16]
  float ln1g[16], ln1b[16], ln2g[16], ln2b[16];
  float wk[2], pad0[2];
  float boP[16];                     // folded b_o + (b_r rows)@Wo
  float B1[64], B2[16];
  // next-layer stage-A params (layer i+1)
  float nLn1g[16], nLn1b[16];
  float nWqlog[4], pad1[4];
  float nWq[512];                    // [d][32] q columns of layer i+1
};
struct alignas(16) CA0 {             // layer-0 stage-A params (for embed fusion)
  float ln1g[16], ln1b[16], wq[4], pad[4];
  float Wq[512];                     // [d][32]
};
struct alignas(16) CGlob {
  float Wemb[kBot * 16];             // [c][16]
  float bemb[16], Wout[16], bout[4], pad[4];
};

__constant__ CParams cP;
__constant__ CA0 cA;
__constant__ CGlob cG;

// ---------------- scratch (device globals; no allocation) ----------------
// x stored blocked-SoA: [b][blk][m(0..3)][t(0..255)] as float4
__device__ float g_x[(size_t)kB * kBPB * 4 * kTPB * 4];
__device__ float4 g_rot[kNP];
__device__ float g_partQ[kGrid * 40];
__device__ float g_partK[kGrid * 40];
__device__ CParams g_banks[kL];
__device__ CA0 g_a0s;
__device__ CGlob g_gls;

// ---------------- packed f32x2 helpers ----------------
__device__ __forceinline__ u64 pack2(float lo, float hi) {
  u64 r; asm("mov.b64 %0,{%1,%2};" : "=l"(r) : "f"(lo), "f"(hi)); return r;
}
__device__ __forceinline__ void unpack2(u64 v, float& lo, float& hi) {
  asm("mov.b64 {%0,%1},%2;" : "=f"(lo), "=f"(hi) : "l"(v));
}
__device__ __forceinline__ u64 fma2(u64 a, u64 b, u64 c) {
  u64 d; asm("fma.rn.f32x2 %0,%1,%2,%3;" : "=l"(d) : "l"(a), "l"(b), "l"(c)); return d;
}
__device__ __forceinline__ void ldc4(const float* p, u64& lo, u64& hi) {
  ulonglong2 v = *reinterpret_cast<const ulonglong2*>(p);
  lo = v.x; hi = v.y;
}

// ---------------- scalar helpers ----------------
__device__ __forceinline__ void ln16(const float* x, const float* g,
                                     const float* bb, float* y) {
  float m = 0.f;
#pragma unroll
  for (int d = 0; d < 16; d++) m += x[d];
  m *= (1.f / 16.f);
  float v = 0.f;
#pragma unroll
  for (int d = 0; d < 16; d++) { float t = x[d] - m; v = fmaf(t, t, v); }
  v *= (1.f / 16.f);
  float r = rsqrtf(v + 1e-5f);
#pragma unroll
  for (int d = 0; d < 16; d++) y[d] = (x[d] - m) * r * g[d] + bb[d];
}

__device__ __forceinline__ void rot_cs(int n, float& c0, float& s0,
                                       float& c1, float& s1) {
  float nf = (float)n;
  float p0 = nf * 3.14159265358979323846f;
  float p1 = nf * 15.70796326794896619231f;
  double d0 = (double)p0 - (double)n * 3.14159265358979323846;
  double d1 = (double)p1 - (double)n * 15.70796326794896619231;
  float e0 = (float)d0, e1 = (float)d1;
  float sgn = (n & 1) ? -1.f : 1.f;
  c0 = sgn * (1.f - 0.5f * e0 * e0);
  s0 = sgn * e0 * (1.f - 0.1666666667f * e0 * e0);
  c1 = sgn * (1.f - 0.5f * e1 * e1);
  s1 = sgn * e1 * (1.f - 0.1666666667f * e1 * e1);
}

__device__ __forceinline__ float gelu_fast(float p) {
  float xs = p * 0.7071067811865475f;
  float ax = fabsf(xs);
  float t = __fdividef(1.f, fmaf(0.3275911f, ax, 1.f));
  float poly = t * fmaf(t, fmaf(t, fmaf(t, fmaf(t, 1.061405429f,
                   -1.453152027f), 1.421413741f), -0.284496736f),
                   0.254829592f);
  float e = __expf(-ax * ax);
  float er = 1.f - poly * e;
  er = copysignf(er, xs);
  return 0.5f * p * (1.f + er);
}

// block reduction of 40 per-thread floats via smem transpose (paired 64-bit)
__device__ __forceinline__ void reduce40_pairs(const float* vals, float* partOut) {
  __shared__ u64 sT[20 * 257];
  __shared__ float sS[40][12];
  int t = threadIdx.x;
#pragma unroll
  for (int p = 0; p < 20; p++)
    sT[p * 257 + t] = pack2(vals[2*p], vals[2*p+1]);
  __syncthreads();
  if (t < 240) {
    int p = t / 12, sl = t % 12;
    float s0 = 0.f, s1 = 0.f;
    const u64* row = &sT[p * 257];
#pragma unroll
    for (int i = sl; i < kTPB; i += 12) {
      float a, b; unpack2(row[i], a, b);
      s0 += a; s1 += b;
    }
    sS[2*p][sl] = s0; sS[2*p+1][sl] = s1;
  }
  __syncthreads();
  if (t < 40) {
    float s = 0.f;
#pragma unroll
    for (int j = 0; j < 12; j++) s += sS[t][j];
    partOut[t] = s;
  }
}

// inline finalize: reduce per-batch partials -> 32 global weights in smem.
// ALL threads call (contains __syncthreads). Deterministic fixed order.
__device__ __forceinline__ void finalize_inline(const float* part, int b,
                                                float* sg32) {
  __shared__ float sf[40][6];
  int t = threadIdx.x;
  const float* pp = part + (size_t)b * kBPB * 40;
  if (t < 240) {
    int k = t / 6, sl = t % 6;
    float acc = 0.f;
    for (int blk = sl; blk < kBPB; blk += 6) acc += pp[blk*40 + k];
    sf[k][sl] = acc;
  }
  __syncthreads();
  if (t < 32) {
    int h = t >> 2, d = t & 3;
    float den = sf[h*5][0]+sf[h*5][1]+sf[h*5][2]+sf[h*5][3]+sf[h*5][4]+sf[h*5][5];
    int r = h*5 + 1 + d;
    float num = sf[r][0]+sf[r][1]+sf[r][2]+sf[r][3]+sf[r][4]+sf[r][5];
    sg32[t] = num / den;
  }
  __syncthreads();
}

__device__ __forceinline__ float4* xblock(int b, int blk) {
  return reinterpret_cast<float4*>(g_x) + ((size_t)(b * kBPB + blk) * 4) * kTPB;
}

// stage-A statistics: LN1 -> q (32 cols) -> rotary + q-logit softmax partials.
__device__ __forceinline__ void qstats_reduce(
    const float* x, bool active, int n,
    const float* lg, const float* lb, const float* Wq, const float* wql,
    float* partOut) {
  float y[16];
  ln16(x, lg, lb, y);
  float4 rt = g_rot[n];
  float vals[40];
#pragma unroll
  for (int hp = 0; hp < 2; hp++) {
    u64 a[8];
#pragma unroll
    for (int m = 0; m < 8; m++) a[m] = 0ull;
#pragma unroll
    for (int d = 0; d < 16; d++) {
      u64 yd = pack2(y[d], y[d]);
      const float* row = &Wq[d * 32 + hp * 16];
#pragma unroll
      for (int h2 = 0; h2 < 4; h2++) {
        u64 w0, w1; ldc4(row + 4 * h2, w0, w1);
        a[2*h2]   = fma2(w0, yd, a[2*h2]);
        a[2*h2+1] = fma2(w1, yd, a[2*h2+1]);
      }
    }
#pragma unroll
    for (int h2 = 0; h2 < 4; h2++) {
      int h = hp * 4 + h2;
      float q0, q1, q2, q3;
      unpack2(a[2*h2], q0, q1); unpack2(a[2*h2+1], q2, q3);
      float lgt = (q0*wql[0] + q1*wql[1] + q2*wql[2] + q3*wql[3]) * kScale;
      float e = active ? __expf(lgt) : 0.f;
      vals[h*5+0] = e;
      vals[h*5+1] = e * (q0*rt.x - q1*rt.y);
      vals[h*5+2] = e * (q1*rt.x + q0*rt.y);
      vals[h*5+3] = e * (q2*rt.z - q3*rt.w);
      vals[h*5+4] = e * (q3*rt.z + q2*rt.w);
    }
  }
  reduce40_pairs(vals, partOut);
}

// ---------------- prep kernels ----------------
__global__ void rotprep_kernel() {
  int n = blockIdx.x * kTPB + threadIdx.x;
  float c0, s0, c1, s1; rot_cs(n, c0, s0, c1, s1);
  g_rot[n] = make_float4(c0, s0, c1, s1);
}

__global__ void gather_kernel(
    const float* __restrict__ Wqkv, const float* __restrict__ ln1g,
    const float* __restrict__ ln1b, const float* __restrict__ wq,
    const float* __restrict__ wk, const float* __restrict__ Wr,
    const float* __restrict__ br, const float* __restrict__ Wo,
    const float* __restrict__ bo, const float* __restrict__ ln2g,
    const float* __restrict__ ln2b, const float* __restrict__ W1,
    const float* __restrict__ b1, const float* __restrict__ W2,
    const float* __restrict__ b2, const float* __restrict__ Wemb,
    const float* __restrict__ bemb, const float* __restrict__ Wout,
    const float* __restrict__ bout) {
  int i = blockIdx.x;
  int t = threadIdx.x;
  if (i < kL) {
    CParams* s = &g_banks[i];
    for (int k = t; k < 1536; k += kTPB) s->Wqkv[k] = Wqkv[i*1536 + k];
    for (int k = t; k < 1024; k += kTPB) s->W1[k]  = W1[i*1024 + k];
    for (int k = t; k < 1024; k += kTPB) s->W2[k]  = W2[i*1024 + k];
    // folded WqWo[d][e] = sum_c Wq[d][c] * Wo[c][e]
    {
      int d = t >> 4, e = t & 15;
      float acc = 0.f;
      for (int c = 0; c < 32; c++)
        acc += Wqkv[i*1536 + d*96 + c] * Wo[i*512 + c*16 + e];
      s->WqWo[t] = acc;
    }
    // folded WrWo[(h*2+p)][e] = sum_j Wr[p][j] * Wo[(4h+j)][e]
    {
      int h = t >> 5, p = (t >> 4) & 1, e = t & 15;
      float acc = 0.f;
      for (int j = 0; j < 4; j++)
        acc += Wr[i*8 + p*4 + j] * Wo[i*512 + (4*h + j)*16 + e];
      s->WrWo[t] = acc;
    }
    // folded boP[e] = bo[e] + sum_{h,j} br[j]*Wo[(4h+j)][e]
    if (t < 16) {
      float acc = bo[i*16 + t];
      for (int h = 0; h < 8; h++)
        for (int j = 0; j < 4; j++)
          acc += br[i*4 + j] * Wo[i*512 + (4*h + j)*16 + t];
      s->boP[t] = acc;
    }
    int jn = (i + 1 < kL) ? i + 1 : i;
    for (int k = t; k < 512; k += kTPB) {
      int d = k >> 5, c = k & 31;
      s->nWq[k] = Wqkv[jn*1536 + d*96 + c];
    }
    if (t < 16) {
      s->ln1g[t] = ln1g[i*16+t]; s->ln1b[t] = ln1b[i*16+t];
      s->ln2g[t] = ln2g[i*16+t]; s->ln2b[t] = ln2b[i*16+t];
      s->B2[t] = b2[i*16+t];
      s->nLn1g[t] = ln1g[jn*16+t]; s->nLn1b[t] = ln1b[jn*16+t];
    }
    if (t < 64) s->B1[t] = b1[i*64+t];
    if (t < 4)  s->nWqlog[t] = wq[jn*4+t];
    if (t < 2)  s->wk[t] = wk[i*2+t];
  } else {
    for (int k = t; k < 512; k += kTPB) {
      int d = k >> 5, c = k & 31;
      g_a0s.Wq[k] = Wqkv[d*96 + c];
    }
    if (t < 16) { g_a0s.ln1g[t] = ln1g[t]; g_a0s.ln1b[t] = ln1b[t]; }
    if (t < 4)  g_a0s.wq[t] = wq[t];
    for (int k = t; k < kBot*16; k += kTPB) g_gls.Wemb[k] = Wemb[k];
    if (t < 16) { g_gls.bemb[t] = bemb[t]; g_gls.Wout[t] = Wout[t]; }
    if (t == 0) g_gls.bout[0] = bout[0];
  }
}

// ---------------- fused embed + stage-A(layer 0) ----------------
__global__ void __launch_bounds__(kTPB) fusedEmbedA_kernel(const float* __restrict__ corr) {
  int b = blockIdx.x / kBPB;
  int blk = blockIdx.x % kBPB;
  int t = threadIdx.x;
  int n = blk * kTPB + t;
  bool active = n < kN;
  float x[16];
  if (active) {
    u64 acc[8];
#pragma unroll
    for (int m = 0; m < 4; m++) ldc4(&cG.bemb[4*m], acc[2*m], acc[2*m+1]);
    const float* cp = corr + (size_t)b * kBot * kN + n;
#pragma unroll 13
    for (int c = 0; c < kBot; c++) {
      float v = fmaxf(cp[(size_t)c * kN], 0.f);
      u64 v2 = pack2(v, v);
#pragma unroll
      for (int m = 0; m < 4; m++) {
        u64 w0, w1; ldc4(&cG.Wemb[c*16 + 4*m], w0, w1);
        acc[2*m]   = fma2(w0, v2, acc[2*m]);
        acc[2*m+1] = fma2(w1, v2, acc[2*m+1]);
      }
    }
#pragma unroll
    for (int m = 0; m < 8; m++) unpack2(acc[m], x[2*m], x[2*m+1]);
  } else {
#pragma unroll
    for (int d = 0; d < 16; d++) x[d] = 0.f;
  }
  float4* xb = xblock(b, blk);
#pragma unroll
  for (int m = 0; m < 4; m++)
    xb[m * kTPB + t] = make_float4(x[4*m], x[4*m+1], x[4*m+2], x[4*m+3]);
  qstats_reduce(x, active, n, cA.ln1g, cA.ln1b, cA.Wq, cA.wq,
                g_partQ + (size_t)blockIdx.x * 40);
}

// ---------------- stage B: inline finalize-Q + k stats ----------------
__global__ void __launch_bounds__(kTPB) stageB_kernel() {
  __shared__ float sgq[32];
  int b = blockIdx.x / kBPB;
  int blk = blockIdx.x % kBPB;
  int t = threadIdx.x;
  finalize_inline(g_partQ, b, sgq);
  int n = blk * kTPB + t;
  bool active = n < kN;
  float x[16];
  const float4* xb = xblock(b, blk);
#pragma unroll
  for (int m = 0; m < 4; m++) {
    float4 t4 = xb[m * kTPB + t];
    x[4*m] = t4.x; x[4*m+1] = t4.y; x[4*m+2] = t4.z; x[4*m+3] = t4.w;
  }
  float y[16];
  ln16(x, cP.ln1g, cP.ln1b, y);
  float4 rt = g_rot[n];
  float vals[40];
#pragma unroll
  for (int hp = 0; hp < 2; hp++) {
    u64 a[8];
#pragma unroll
    for (int m = 0; m < 8; m++) a[m] = 0ull;
#pragma unroll
    for (int d = 0; d < 16; d++) {
      u64 yd = pack2(y[d], y[d]);
      const float* row = &cP.Wqkv[d*96 + 32 + hp*16];
#pragma unroll
      for (int h2 = 0; h2 < 4; h2++) {
        u64 w0, w1; ldc4(row + 4*h2, w0, w1);
        a[2*h2]   = fma2(w0, yd, a[2*h2]);
        a[2*h2+1] = fma2(w1, yd, a[2*h2+1]);
      }
    }
#pragma unroll
    for (int h2 = 0; h2 < 4; h2++) {
      int h = hp * 4 + h2;
      float k0, k1, k2v, k3;
      unpack2(a[2*h2], k0, k1); unpack2(a[2*h2+1], k2v, k3);
      float p0 = k0*sgq[4*h+0] + k1*sgq[4*h+1];
      float p1 = k2v*sgq[4*h+2] + k3*sgq[4*h+3];
      float lgt = (p0*cP.wk[0] + p1*cP.wk[1]) * kScale;
      float e = active ? __expf(lgt) : 0.f;
      vals[h*5+0] = e;
      vals[h*5+1] = e * (k0*rt.x - k1*rt.y);
      vals[h*5+2] = e * (k1*rt.x + k0*rt.y);
      vals[h*5+3] = e * (k2v*rt.z - k3*rt.w);
      vals[h*5+4] = e * (k3*rt.z + k2v*rt.w);
    }
  }
  reduce40_pairs(vals, g_partK + (size_t)blockIdx.x * 40);
}

// ---------------- fused: inline finalize-K + stage C + stage-A(next) ----------------
__global__ void __launch_bounds__(kTPB) fusedCA_kernel(float* __restrict__ out,
                                                       int last, int do_stats) {
  __shared__ float sgk[32];
  int b = blockIdx.x / kBPB;
  int blk = blockIdx.x % kBPB;
  int t = threadIdx.x;
  finalize_inline(g_partK, b, sgk);
  int n = blk * kTPB + t;
  bool active = n < kN;
  float4* xb = xblock(b, blk);
  float x[16];
#pragma unroll
  for (int m = 0; m < 4; m++) {
    float4 t4 = xb[m * kTPB + t];
    x[4*m] = t4.x; x[4*m+1] = t4.y; x[4*m+2] = t4.z; x[4*m+3] = t4.w;
  }
  float y[16];
  ln16(x, cP.ln1g, cP.ln1b, y);

  // v = y @ Wv (cols 64..95)
  u64 av[16];
#pragma unroll
  for (int m = 0; m < 16; m++) av[m] = 0ull;
#pragma unroll
  for (int d = 0; d < 16; d++) {
    u64 yd = pack2(y[d], y[d]);
    const float* row = &cP.Wqkv[d*96 + 64];
#pragma unroll
    for (int m = 0; m < 8; m++) {
      u64 w0, w1; ldc4(row + 4*m, w0, w1);
      av[2*m]   = fma2(w0, yd, av[2*m]);
      av[2*m+1] = fma2(w1, yd, av[2*m+1]);
    }
  }
  float v[32];
#pragma unroll
  for (int m = 0; m < 16; m++) unpack2(av[m], v[2*m], v[2*m+1]);

  // u[h][p] = paired v * global_k
  float u[16];
#pragma unroll
  for (int h = 0; h < 8; h++) {
    u[2*h]   = v[4*h+0]*sgk[4*h+0] + v[4*h+1]*sgk[4*h+1];
    u[2*h+1] = v[4*h+2]*sgk[4*h+2] + v[4*h+3]*sgk[4*h+3];
  }

  // x += boP + y@WqWo + u@WrWo   (all folded)
  u64 ao[8];
#pragma unroll
  for (int m = 0; m < 4; m++) ldc4(&cP.boP[4*m], ao[2*m], ao[2*m+1]);
#pragma unroll
  for (int d = 0; d < 16; d++) {
    u64 yd = pack2(y[d], y[d]);
    const float* row = &cP.WqWo[d*16];
#pragma unroll
    for (int m = 0; m < 4; m++) {
      u64 w0, w1; ldc4(row + 4*m, w0, w1);
      ao[2*m]   = fma2(w0, yd, ao[2*m]);
      ao[2*m+1] = fma2(w1, yd, ao[2*m+1]);
    }
  }
#pragma unroll
  for (int hp = 0; hp < 16; hp++) {
    u64 uc = pack2(u[hp], u[hp]);
    const float* row = &cP.WrWo[hp*16];
#pragma unroll
    for (int m = 0; m < 4; m++) {
      u64 w0, w1; ldc4(row + 4*m, w0, w1);
      ao[2*m]   = fma2(w0, uc, ao[2*m]);
      ao[2*m+1] = fma2(w1, uc, ao[2*m+1]);
    }
  }
#pragma unroll
  for (int m = 0; m < 8; m++) {
    float a0, a1; unpack2(ao[m], a0, a1);
    x[2*m] += a0; x[2*m+1] += a1;
  }

  // FF block, 2 chunks of 32 hidden units
  float y2[16];
  ln16(x, cP.ln2g, cP.ln2b, y2);
  u64 a2[8];
#pragma unroll
  for (int m = 0; m < 4; m++) ldc4(&cP.B2[4*m], a2[2*m], a2[2*m+1]);
#pragma unroll
  for (int jc = 0; jc < 2; jc++) {
    u64 hh[16];
#pragma unroll
    for (int m = 0; m < 8; m++) ldc4(&cP.B1[jc*32 + 4*m], hh[2*m], hh[2*m+1]);
#pragma unroll
    for (int d = 0; d < 16; d++) {
      u64 yd = pack2(y2[d], y2[d]);
      const float* row = &cP.W1[d*64 + jc*32];
#pragma unroll
      for (int m = 0; m < 8; m++) {
        u64 w0, w1; ldc4(row + 4*m, w0, w1);
        hh[2*m]   = fma2(w0, yd, hh[2*m]);
        hh[2*m+1] = fma2(w1, yd, hh[2*m+1]);
      }
    }
#pragma unroll
    for (int m = 0; m < 16; m++) {
      float p0, p1; unpack2(hh[m], p0, p1);
      float g0 = gelu_fast(p0);
      float g1 = gelu_fast(p1);
      int j0 = jc*32 + 2*m;
      u64 h0 = pack2(g0, g0);
      const float* w2r = &cP.W2[j0*16];
#pragma unroll
      for (int mm = 0; mm < 4; mm++) {
        u64 w0, w1; ldc4(w2r + 4*mm, w0, w1);
        a2[2*mm]   = fma2(w0, h0, a2[2*mm]);
        a2[2*mm+1] = fma2(w1, h0, a2[2*mm+1]);
      }
      u64 h1 = pack2(g1, g1);
      w2r += 16;
#pragma unroll
      for (int mm = 0; mm < 4; mm++) {
        u64 w0, w1; ldc4(w2r + 4*mm, w0, w1);
        a2[2*mm]   = fma2(w0, h1, a2[2*mm]);
        a2[2*mm+1] = fma2(w1, h1, a2[2*mm+1]);
      }
    }
  }
#pragma unroll
  for (int m = 0; m < 8; m++) {
    float a0, a1; unpack2(a2[m], a0, a1);
    x[2*m] += a0; x[2*m+1] += a1;
  }

  if (last) {
    if (active) {
      float o = cG.bout[0];
#pragma unroll
      for (int d = 0; d < 16; d++) o = fmaf(x[d], cG.Wout[d], o);
      out[(size_t)b * kN + n] = o;
    }
  } else {
#pragma unroll
    for (int m = 0; m < 4; m++)
      xb[m * kTPB + t] = make_float4(x[4*m], x[4*m+1], x[4*m+2], x[4*m+3]);
  }
  if (do_stats) {
    qstats_reduce(x, active, n, cP.nLn1g, cP.nLn1b, cP.nWq, cP.nWqlog,
                  g_partQ + (size_t)blockIdx.x * 40);
  }
}

// ---------------- host launcher ----------------
extern "C" void kernel_launch(void* const* d_in, const int* in_sizes, int n_in,
                              void* d_out, int out_size) {
  (void)in_sizes; (void)n_in; (void)out_size;
  const float* corr  = (const float*)d_in[0];
  const float* W_emb = (const float*)d_in[1];
  const float* b_emb = (const float*)d_in[2];
  const float* ln1_g = (const float*)d_in[3];
  const float* ln1_b = (const float*)d_in[4];
  const float* W_qkv = (const float*)d_in[5];
  const float* w_qlog= (const float*)d_in[6];
  const float* w_klog= (const float*)d_in[7];
  const float* W_r   = (const float*)d_in[8];
  const float* b_r   = (const float*)d_in[9];
  const float* W_o   = (const float*)d_in[10];
  const float* b_o   = (const float*)d_in[11];
  const float* ln2_g = (const float*)d_in[12];
  const float* ln2_b = (const float*)d_in[13];
  const float* W_ff1 = (const float*)d_in[14];
  const float* b_ff1 = (const float*)d_in[15];
  const float* W_ff2 = (const float*)d_in[16];
  const float* b_ff2 = (const float*)d_in[17];
  const float* W_out = (const float*)d_in[18];
  const float* b_out = (const float*)d_in[19];
  float* out = (float*)d_out;

  rotprep_kernel<<<kBPB, kTPB>>>();
  gather_kernel<<<kL + 1, kTPB>>>(W_qkv, ln1_g, ln1_b, w_qlog, w_klog, W_r,
                                  b_r, W_o, b_o, ln2_g, ln2_b, W_ff1, b_ff1,
                                  W_ff2, b_ff2, W_emb, b_emb, W_out, b_out);

  void *pBanks = nullptr, *pA0 = nullptr, *pGl = nullptr;
  cudaGetSymbolAddress(&pBanks, g_banks);
  cudaGetSymbolAddress(&pA0, g_a0s);
  cudaGetSymbolAddress(&pGl, g_gls);

  cudaMemcpyToSymbolAsync(cG, pGl, sizeof(CGlob), 0, cudaMemcpyDeviceToDevice, 0);
  cudaMemcpyToSymbolAsync(cA, pA0, sizeof(CA0), 0, cudaMemcpyDeviceToDevice, 0);
  cudaMemcpyToSymbolAsync(cP, pBanks, sizeof(CParams), 0,
                          cudaMemcpyDeviceToDevice, 0);

  fusedEmbedA_kernel<<<kGrid, kTPB>>>(corr);

  for (int i = 0; i < kL; i++) {
    stageB_kernel<<<kGrid, kTPB>>>();
    fusedCA_kernel<<<kGrid, kTPB>>>(out, (i == kL - 1) ? 1 : 0,
                                    (i < kL - 1) ? 1 : 0);
    if (i + 1 < kL) {
      cudaMemcpyToSymbolAsync(
          cP, (const char*)pBanks + (size_t)(i + 1) * sizeof(CParams),
          sizeof(CParams), 0, cudaMemcpyDeviceToDevice, 0);
    }
  }
}